// round 1
// baseline (speedup 1.0000x reference)
#include <cuda_runtime.h>
#include <math.h>

#define NL 4
#define NB 4
#define NS 1024
#define ND 768
#define NF 3072
#define NE 4
#define NV 256
#define NH 12
#define NDH 64
#define NT (NB*NS)

// ---------------- scratch (device globals; no allocation allowed) ----------------
__device__ float g_x[NT*ND];
__device__ float g_h[NT*ND];
__device__ float g_q[NT*ND];
__device__ float g_k[NT*ND];
__device__ float g_v[NT*ND];
__device__ float g_o[NT*ND];
__device__ float g_sc[(size_t)NB*NH*NS*NS];   // attention scores, 192 MB
__device__ float g_xc[NT*3*ND];               // im2col for conv
__device__ float g_wc[3*ND*ND];               // repacked conv weight [3D, D]
__device__ float g_h1[NT*NF];                 // expert hidden
__device__ float g_gate[NT*NE];               // top-2 renormalized gates (zeros elsewhere)

__device__ __forceinline__ float gelu_f(float x){
    const float c = 0.7978845608028654f; // sqrt(2/pi), tanh-approx gelu (jax default)
    return 0.5f*x*(1.0f + tanhf(c*(x + 0.044715f*x*x*x)));
}

// ---------------- embedding lookup ----------------
__global__ void embed_kernel(const int* __restrict__ text, const float* __restrict__ emb){
    int t = blockIdx.x;
    int tok = text[t];
    const float* src = emb + (size_t)tok*ND;
    float* dst = g_x + (size_t)t*ND;
    for (int d = threadIdx.x; d < ND; d += blockDim.x) dst[d] = src[d];
}

// conv_w (D,D,3) [o][i][k]  ->  g_wc [(k*D+i)][o]   so conv becomes xcat @ wc
__global__ void repack_conv_kernel(const float* __restrict__ w){
    int idx = blockIdx.x*blockDim.x + threadIdx.x;
    if (idx >= 3*ND*ND) return;
    int o = idx % ND;
    int r = idx / ND;
    int i = r % ND;
    int k = r / ND;
    g_wc[idx] = w[((size_t)o*ND + i)*3 + k];
}

// xcat[t, k*D+i] = x[t+k-1, i] within the same batch row (SAME padding)
__global__ void xcat_kernel(){
    int t = blockIdx.x;
    int s = t % NS;
    float* dst = g_xc + (size_t)t*3*ND;
    for (int idx = threadIdx.x; idx < 3*ND; idx += blockDim.x) {
        int k = idx / ND, i = idx % ND;
        int sp = s + k - 1;
        dst[idx] = (sp >= 0 && sp < NS) ? g_x[(size_t)(t + k - 1)*ND + i] : 0.0f;
    }
}

// ---------------- layernorm (two-pass, eps=1e-5) ----------------
__global__ void ln_kernel(const float* __restrict__ x, const float* __restrict__ g,
                          const float* __restrict__ b, float* __restrict__ out){
    __shared__ float red[256];
    int r = blockIdx.x;
    const float* xr = x + (size_t)r*ND;
    int tid = threadIdx.x;
    float s = 0.f;
    for (int d = tid; d < ND; d += 256) s += xr[d];
    red[tid] = s; __syncthreads();
    for (int o = 128; o > 0; o >>= 1){ if (tid < o) red[tid] += red[tid+o]; __syncthreads(); }
    float mean = red[0] / (float)ND;
    __syncthreads();
    float vs = 0.f;
    for (int d = tid; d < ND; d += 256){ float dd = xr[d]-mean; vs += dd*dd; }
    red[tid] = vs; __syncthreads();
    for (int o = 128; o > 0; o >>= 1){ if (tid < o) red[tid] += red[tid+o]; __syncthreads(); }
    float rstd = rsqrtf(red[0]/(float)ND + 1e-5f);
    float* orow = out + (size_t)r*ND;
    for (int d = tid; d < ND; d += 256)
        orow[d] = (xr[d]-mean)*rstd*g[d] + b[d];
}

// ---------------- row softmax over S=1024 (for attention scores) ----------------
__global__ void softmax_kernel(){
    __shared__ float red[256];
    size_t row = blockIdx.x;
    float* p = g_sc + row*(size_t)NS;
    int tid = threadIdx.x;
    float m = -1e30f;
    for (int d = tid; d < NS; d += 256) m = fmaxf(m, p[d]);
    red[tid]=m; __syncthreads();
    for (int o=128;o>0;o>>=1){ if(tid<o) red[tid]=fmaxf(red[tid],red[tid+o]); __syncthreads(); }
    m = red[0]; __syncthreads();
    float s=0.f;
    for (int d = tid; d < NS; d += 256){ float e = expf(p[d]-m); p[d]=e; s+=e; }
    red[tid]=s; __syncthreads();
    for (int o=128;o>0;o>>=1){ if(tid<o) red[tid]+=red[tid+o]; __syncthreads(); }
    float inv = 1.0f/red[0];
    for (int d = tid; d < NS; d += 256) p[d] *= inv;
}

// ---------------- router: logits -> softmax -> top2 -> renormalized gates ----------------
__global__ void router_kernel(const float* __restrict__ h, const float* __restrict__ rw,
                              const float* __restrict__ rb){
    int t = blockIdx.x*blockDim.y + threadIdx.y;
    int lane = threadIdx.x;
    float a0=0.f,a1=0.f,a2=0.f,a3=0.f;
    const float* hr = h + (size_t)t*ND;
    for (int d = lane; d < ND; d += 32){
        float hv = hr[d];
        a0 += hv*rw[d*NE+0];
        a1 += hv*rw[d*NE+1];
        a2 += hv*rw[d*NE+2];
        a3 += hv*rw[d*NE+3];
    }
    #pragma unroll
    for (int o=16;o>0;o>>=1){
        a0 += __shfl_down_sync(0xffffffffu, a0, o);
        a1 += __shfl_down_sync(0xffffffffu, a1, o);
        a2 += __shfl_down_sync(0xffffffffu, a2, o);
        a3 += __shfl_down_sync(0xffffffffu, a3, o);
    }
    if (lane==0){
        float l[4]={a0+rb[0],a1+rb[1],a2+rb[2],a3+rb[3]};
        float lm = fmaxf(fmaxf(l[0],l[1]),fmaxf(l[2],l[3]));
        float p[4]; float sum=0.f;
        #pragma unroll
        for(int e=0;e<4;e++){ p[e]=expf(l[e]-lm); sum+=p[e]; }
        #pragma unroll
        for(int e=0;e<4;e++) p[e]/=sum;
        int i0=0;
        #pragma unroll
        for(int e=1;e<4;e++) if(p[e]>p[i0]) i0=e;
        int i1=-1;
        #pragma unroll
        for(int e=0;e<4;e++){ if(e==i0) continue; if(i1<0 || p[e]>p[i1]) i1=e; }
        float gs = p[i0]+p[i1];
        float outv[4]={0.f,0.f,0.f,0.f};
        outv[i0]=p[i0]/gs; outv[i1]=p[i1]/gs;
        #pragma unroll
        for(int e=0;e<4;e++) g_gate[(size_t)t*NE+e]=outv[e];
    }
}

// ---------------- generic tiled SGEMM with fused epilogue ----------------
// C[M,N] (+)= rowscale[m] * act( alpha * A@B(^T) + bias[n] )
// batched over blockIdx.z with offset = (z/hdiv)*s?o + (z%hdiv)*s?i
__global__ void __launch_bounds__(256) gemm_kernel(
    const float* __restrict__ A, int lda, long long sAo, long long sAi,
    const float* __restrict__ Bm, int ldb, long long sBo, long long sBi, int transB,
    float* C, int ldc, long long sCo, long long sCi,
    int M, int N, int K, int hdiv,
    float alpha, const float* __restrict__ bias, int act,
    const float* __restrict__ rowscale, int rs_stride, int accum)
{
    int z = blockIdx.z;
    int zo = z / hdiv, zi = z - zo*hdiv;
    A  += zo*sAo + zi*sAi;
    Bm += zo*sBo + zi*sBi;
    C  += zo*sCo + zi*sCi;

    __shared__ float As[16][64];
    __shared__ float Bs[16][64];

    int tid = threadIdx.x;
    int row0 = (tid >> 4) * 4;
    int col0 = (tid & 15) * 4;
    int m0 = blockIdx.y * 64;
    int n0 = blockIdx.x * 64;

    float acc[4][4];
    #pragma unroll
    for (int i=0;i<4;i++)
        #pragma unroll
        for(int j=0;j<4;j++) acc[i][j]=0.f;

    int am = tid >> 2;          // A: 64 rows x 4 threads each loading float4 along K
    int ak = (tid & 3) * 4;
    int bn_t = tid >> 2;        // transB: 64 cols x float4 along K
    int bk_t = (tid & 3) * 4;
    int bk = tid >> 4;          // !transB: 16 K-rows x float4 along N
    int bn = (tid & 15) * 4;

    for (int k0 = 0; k0 < K; k0 += 16) {
        float4 av = *(const float4*)(A + (long long)(m0+am)*lda + (k0+ak));
        As[ak+0][am]=av.x; As[ak+1][am]=av.y; As[ak+2][am]=av.z; As[ak+3][am]=av.w;
        if (transB) {
            float4 bv = *(const float4*)(Bm + (long long)(n0+bn_t)*ldb + (k0+bk_t));
            Bs[bk_t+0][bn_t]=bv.x; Bs[bk_t+1][bn_t]=bv.y; Bs[bk_t+2][bn_t]=bv.z; Bs[bk_t+3][bn_t]=bv.w;
        } else {
            float4 bv = *(const float4*)(Bm + (long long)(k0+bk)*ldb + (n0+bn));
            *(float4*)&Bs[bk][bn] = bv;
        }
        __syncthreads();
        #pragma unroll
        for (int kk=0;kk<16;kk++){
            float4 a = *(const float4*)&As[kk][row0];
            float4 b = *(const float4*)&Bs[kk][col0];
            acc[0][0]+=a.x*b.x; acc[0][1]+=a.x*b.y; acc[0][2]+=a.x*b.z; acc[0][3]+=a.x*b.w;
            acc[1][0]+=a.y*b.x; acc[1][1]+=a.y*b.y; acc[1][2]+=a.y*b.z; acc[1][3]+=a.y*b.w;
            acc[2][0]+=a.z*b.x; acc[2][1]+=a.z*b.y; acc[2][2]+=a.z*b.z; acc[2][3]+=a.z*b.w;
            acc[3][0]+=a.w*b.x; acc[3][1]+=a.w*b.y; acc[3][2]+=a.w*b.z; acc[3][3]+=a.w*b.w;
        }
        __syncthreads();
    }

    #pragma unroll
    for (int i=0;i<4;i++){
        int m = m0 + row0 + i;
        float rs = rowscale ? rowscale[(long long)m*rs_stride] : 1.0f;
        #pragma unroll
        for (int j=0;j<4;j++){
            int n = n0 + col0 + j;
            float v = alpha*acc[i][j];
            if (bias) v += bias[n];
            if (act) v = gelu_f(v);
            v *= rs;
            long long idx = (long long)m*ldc + n;
            if (accum) C[idx] += v; else C[idx] = v;
        }
    }
}

static void launch_gemm(const float*A,int lda,long long sAo,long long sAi,
  const float*Bp,int ldb,long long sBo,long long sBi,int transB,
  float*C,int ldc,long long sCo,long long sCi,
  int M,int N,int K,int batch,int hdiv,
  float alpha,const float*bias,int act,const float*rs,int rss,int accum)
{
    dim3 grid((unsigned)(N/64), (unsigned)(M/64), (unsigned)batch);
    gemm_kernel<<<grid,256>>>(A,lda,sAo,sAi,Bp,ldb,sBo,sBi,transB,C,ldc,sCo,sCi,
                              M,N,K,hdiv,alpha,bias,act,rs,rss,accum);
}

extern "C" void kernel_launch(void* const* d_in, const int* in_sizes, int n_in,
                              void* d_out, int out_size)
{
    (void)in_sizes; (void)n_in; (void)out_size;
    const int*   text  = (const int*)  d_in[0];
    const float* embed = (const float*)d_in[1];
    const float* conv_w= (const float*)d_in[2];
    const float* conv_b= (const float*)d_in[3];
    const float* Wq    = (const float*)d_in[4];
    const float* bq    = (const float*)d_in[5];
    const float* Wk    = (const float*)d_in[6];
    const float* bk    = (const float*)d_in[7];
    const float* Wv    = (const float*)d_in[8];
    const float* bv    = (const float*)d_in[9];
    const float* Wo    = (const float*)d_in[10];
    const float* bo    = (const float*)d_in[11];
    const float* rw    = (const float*)d_in[12];
    const float* rb    = (const float*)d_in[13];
    const float* ew1   = (const float*)d_in[14];
    const float* eb1   = (const float*)d_in[15];
    const float* ew2   = (const float*)d_in[16];
    const float* eb2   = (const float*)d_in[17];
    const float* ln1g  = (const float*)d_in[18];
    const float* ln1b  = (const float*)d_in[19];
    const float* ln2g  = (const float*)d_in[20];
    const float* ln2b  = (const float*)d_in[21];
    const float* lnfg  = (const float*)d_in[22];
    const float* lnfb  = (const float*)d_in[23];
    const float* outw  = (const float*)d_in[24];
    const float* outb  = (const float*)d_in[25];
    float* out = (float*)d_out;

    float *x,*h,*q,*k,*v,*o,*sc,*xc,*wc,*h1,*gate;
    cudaGetSymbolAddress((void**)&x,  g_x);
    cudaGetSymbolAddress((void**)&h,  g_h);
    cudaGetSymbolAddress((void**)&q,  g_q);
    cudaGetSymbolAddress((void**)&k,  g_k);
    cudaGetSymbolAddress((void**)&v,  g_v);
    cudaGetSymbolAddress((void**)&o,  g_o);
    cudaGetSymbolAddress((void**)&sc, g_sc);
    cudaGetSymbolAddress((void**)&xc, g_xc);
    cudaGetSymbolAddress((void**)&wc, g_wc);
    cudaGetSymbolAddress((void**)&h1, g_h1);
    cudaGetSymbolAddress((void**)&gate, g_gate);

    // ---- tokenizer: embed + conv1d(SAME) + gelu + residual ----
    embed_kernel<<<NT,256>>>(text, embed);
    repack_conv_kernel<<<(3*ND*ND+255)/256,256>>>(conv_w);
    xcat_kernel<<<NT,256>>>();
    // x += gelu(xcat @ wc + conv_b)
    launch_gemm(xc,3*ND,0,0, wc,ND,0,0,0, x,ND,0,0,
                NT,ND,3*ND, 1,1, 1.0f, conv_b, 1, nullptr,0, 1);

    const long long sQK = (long long)NS*ND;   // per-batch stride in q/k/v/o
    const long long sSC = (long long)NS*NS;   // per-head stride in scores

    for (int i=0;i<NL;i++){
        // ---- attention ----
        ln_kernel<<<NT,256>>>(x, ln1g+(size_t)i*ND, ln1b+(size_t)i*ND, h);
        launch_gemm(h,ND,0,0, Wq+(size_t)i*ND*ND,ND,0,0,0, q,ND,0,0,
                    NT,ND,ND,1,1, 1.0f, bq+(size_t)i*ND, 0, nullptr,0, 0);
        launch_gemm(h,ND,0,0, Wk+(size_t)i*ND*ND,ND,0,0,0, k,ND,0,0,
                    NT,ND,ND,1,1, 1.0f, bk+(size_t)i*ND, 0, nullptr,0, 0);
        launch_gemm(h,ND,0,0, Wv+(size_t)i*ND*ND,ND,0,0,0, v,ND,0,0,
                    NT,ND,ND,1,1, 1.0f, bv+(size_t)i*ND, 0, nullptr,0, 0);
        // scores[b,h] = 0.125 * Q_bh @ K_bh^T
        launch_gemm(q,ND,sQK,NDH, k,ND,sQK,NDH,1,
                    sc,NS,(long long)NH*sSC,sSC,
                    NS,NS,NDH, NB*NH,NH, 0.125f, nullptr,0, nullptr,0, 0);
        softmax_kernel<<<NB*NH*NS,256>>>();
        // O_bh = A_bh @ V_bh
        launch_gemm(sc,NS,(long long)NH*sSC,sSC, v,ND,sQK,NDH,0,
                    o,ND,sQK,NDH,
                    NS,NDH,NS, NB*NH,NH, 1.0f, nullptr,0, nullptr,0, 0);
        // x += o @ Wo + bo
        launch_gemm(o,ND,0,0, Wo+(size_t)i*ND*ND,ND,0,0,0, x,ND,0,0,
                    NT,ND,ND,1,1, 1.0f, bo+(size_t)i*ND, 0, nullptr,0, 1);

        // ---- MoE ----
        ln_kernel<<<NT,256>>>(x, ln2g+(size_t)i*ND, ln2b+(size_t)i*ND, h);
        router_kernel<<<NT/4, dim3(32,4)>>>(h, rw+(size_t)i*ND*NE, rb+(size_t)i*NE);
        for (int e=0;e<NE;e++){
            const float* w1 = ew1 + ((size_t)(i*NE+e))*ND*NF;
            const float* b1 = eb1 + ((size_t)(i*NE+e))*NF;
            const float* w2 = ew2 + ((size_t)(i*NE+e))*NF*ND;
            const float* b2 = eb2 + ((size_t)(i*NE+e))*ND;
            // h1 = gelu(h @ w1 + b1)
            launch_gemm(h,ND,0,0, w1,NF,0,0,0, h1,NF,0,0,
                        NT,NF,ND,1,1, 1.0f, b1, 1, nullptr,0, 0);
            // x += gate[:,e] * (h1 @ w2 + b2)
            launch_gemm(h1,NF,0,0, w2,ND,0,0,0, x,ND,0,0,
                        NT,ND,NF,1,1, 1.0f, b2, 0, gate+e, NE, 1);
        }
    }

    // ---- final LN + output projection ----
    ln_kernel<<<NT,256>>>(x, lnfg, lnfb, h);
    launch_gemm(h,ND,0,0, outw,NV,0,0,0, out,NV,0,0,
                NT,NV,ND,1,1, 1.0f, outb, 0, nullptr,0, 0);
}

// round 2
// speedup vs baseline: 1.2582x; 1.2582x over previous
#include <cuda_runtime.h>
#include <math.h>

#define NL 4
#define NB 4
#define NS 1024
#define ND 768
#define NF 3072
#define NE 4
#define NV 256
#define NH 12
#define NDH 64
#define NT (NB*NS)

// ---------------- packed f32x2 helpers (Blackwell: ptxas never emits these from C++) ----
#define FMA2(d,a,b,c) asm("fma.rn.f32x2 %0, %1, %2, %3;" : "=l"(d) : "l"(a), "l"(b), "l"(c))
#define DUP2(d,s)     asm("mov.b64 %0, {%1, %1};" : "=l"(d) : "f"(s))
#define UNP2(lo,hi,v) asm("mov.b64 {%0, %1}, %2;" : "=f"(lo), "=f"(hi) : "l"(v))

// ---------------- scratch (device globals; no allocation allowed) ----------------
__device__ float g_x[NT*ND];
__device__ float g_h[NT*ND];
__device__ float g_q[NT*ND];
__device__ float g_k[NT*ND];
__device__ float g_v[NT*ND];
__device__ float g_o[NT*ND];
__device__ float g_sc[(size_t)NB*NH*NS*NS];   // attention scores
__device__ float g_xc[NT*3*ND];               // im2col for conv
__device__ float g_wc[3*ND*ND];               // repacked conv weight [3D, D]
__device__ float g_h1[NT*NF];                 // expert hidden (compacted per expert)
__device__ float g_gate[NT*NE];               // top-2 renormalized gates (zeros elsewhere)
__device__ int   g_eidx[NE*NT];               // per-expert compacted token lists
__device__ int   g_ecnt[NE];                  // per-expert token counts

__device__ __forceinline__ float gelu_f(float x){
    const float c = 0.7978845608028654f; // sqrt(2/pi), tanh-approx gelu (jax default)
    return 0.5f*x*(1.0f + tanhf(c*(x + 0.044715f*x*x*x)));
}

// ---------------- embedding lookup ----------------
__global__ void embed_kernel(const int* __restrict__ text, const float* __restrict__ emb){
    int t = blockIdx.x;
    int tok = text[t];
    const float* src = emb + (size_t)tok*ND;
    float* dst = g_x + (size_t)t*ND;
    for (int d = threadIdx.x; d < ND; d += blockDim.x) dst[d] = src[d];
}

// conv_w (D,D,3) [o][i][k]  ->  g_wc [(k*D+i)][o]   so conv becomes xcat @ wc
__global__ void repack_conv_kernel(const float* __restrict__ w){
    int idx = blockIdx.x*blockDim.x + threadIdx.x;
    if (idx >= 3*ND*ND) return;
    int o = idx % ND;
    int r = idx / ND;
    int i = r % ND;
    int k = r / ND;
    g_wc[idx] = w[((size_t)o*ND + i)*3 + k];
}

// xcat[t, k*D+i] = x[t+k-1, i] within the same batch row (SAME padding)
__global__ void xcat_kernel(){
    int t = blockIdx.x;
    int s = t % NS;
    float* dst = g_xc + (size_t)t*3*ND;
    for (int idx = threadIdx.x; idx < 3*ND; idx += blockDim.x) {
        int k = idx / ND, i = idx % ND;
        int sp = s + k - 1;
        dst[idx] = (sp >= 0 && sp < NS) ? g_x[(size_t)(t + k - 1)*ND + i] : 0.0f;
    }
}

// ---------------- layernorm (two-pass, eps=1e-5) ----------------
__global__ void ln_kernel(const float* __restrict__ x, const float* __restrict__ g,
                          const float* __restrict__ b, float* __restrict__ out){
    __shared__ float red[256];
    int r = blockIdx.x;
    const float* xr = x + (size_t)r*ND;
    int tid = threadIdx.x;
    float s = 0.f;
    for (int d = tid; d < ND; d += 256) s += xr[d];
    red[tid] = s; __syncthreads();
    for (int o = 128; o > 0; o >>= 1){ if (tid < o) red[tid] += red[tid+o]; __syncthreads(); }
    float mean = red[0] / (float)ND;
    __syncthreads();
    float vs = 0.f;
    for (int d = tid; d < ND; d += 256){ float dd = xr[d]-mean; vs += dd*dd; }
    red[tid] = vs; __syncthreads();
    for (int o = 128; o > 0; o >>= 1){ if (tid < o) red[tid] += red[tid+o]; __syncthreads(); }
    float rstd = rsqrtf(red[0]/(float)ND + 1e-5f);
    float* orow = out + (size_t)r*ND;
    for (int d = tid; d < ND; d += 256)
        orow[d] = (xr[d]-mean)*rstd*g[d] + b[d];
}

// ---------------- row softmax over S=1024 ----------------
__global__ void softmax_kernel(){
    __shared__ float red[256];
    size_t row = blockIdx.x;
    float* p = g_sc + row*(size_t)NS;
    int tid = threadIdx.x;
    float m = -1e30f;
    for (int d = tid; d < NS; d += 256) m = fmaxf(m, p[d]);
    red[tid]=m; __syncthreads();
    for (int o=128;o>0;o>>=1){ if(tid<o) red[tid]=fmaxf(red[tid],red[tid+o]); __syncthreads(); }
    m = red[0]; __syncthreads();
    float s=0.f;
    for (int d = tid; d < NS; d += 256){ float e = expf(p[d]-m); p[d]=e; s+=e; }
    red[tid]=s; __syncthreads();
    for (int o=128;o>0;o>>=1){ if(tid<o) red[tid]+=red[tid+o]; __syncthreads(); }
    float inv = 1.0f/red[0];
    for (int d = tid; d < NS; d += 256) p[d] *= inv;
}

// ---------------- zero the per-expert counters ----------------
__global__ void zero_cnt_kernel(){
    if (threadIdx.x < NE) g_ecnt[threadIdx.x] = 0;
}

// ---------------- router: softmax -> top2 -> gates + compacted expert lists ------
__global__ void router_kernel(const float* __restrict__ h, const float* __restrict__ rw,
                              const float* __restrict__ rb){
    int t = blockIdx.x*blockDim.y + threadIdx.y;
    int lane = threadIdx.x;
    float a0=0.f,a1=0.f,a2=0.f,a3=0.f;
    const float* hr = h + (size_t)t*ND;
    for (int d = lane; d < ND; d += 32){
        float hv = hr[d];
        a0 += hv*rw[d*NE+0];
        a1 += hv*rw[d*NE+1];
        a2 += hv*rw[d*NE+2];
        a3 += hv*rw[d*NE+3];
    }
    #pragma unroll
    for (int o=16;o>0;o>>=1){
        a0 += __shfl_down_sync(0xffffffffu, a0, o);
        a1 += __shfl_down_sync(0xffffffffu, a1, o);
        a2 += __shfl_down_sync(0xffffffffu, a2, o);
        a3 += __shfl_down_sync(0xffffffffu, a3, o);
    }
    if (lane==0){
        float l[4]={a0+rb[0],a1+rb[1],a2+rb[2],a3+rb[3]};
        float lm = fmaxf(fmaxf(l[0],l[1]),fmaxf(l[2],l[3]));
        float p[4]; float sum=0.f;
        #pragma unroll
        for(int e=0;e<4;e++){ p[e]=expf(l[e]-lm); sum+=p[e]; }
        #pragma unroll
        for(int e=0;e<4;e++) p[e]/=sum;
        int i0=0;
        #pragma unroll
        for(int e=1;e<4;e++) if(p[e]>p[i0]) i0=e;
        int i1=-1;
        #pragma unroll
        for(int e=0;e<4;e++){ if(e==i0) continue; if(i1<0 || p[e]>p[i1]) i1=e; }
        float gs = p[i0]+p[i1];
        float outv[4]={0.f,0.f,0.f,0.f};
        outv[i0]=p[i0]/gs; outv[i1]=p[i1]/gs;
        #pragma unroll
        for(int e=0;e<4;e++) g_gate[(size_t)t*NE+e]=outv[e];
        int pos0 = atomicAdd(&g_ecnt[i0], 1); g_eidx[i0*NT+pos0]=t;
        int pos1 = atomicAdd(&g_ecnt[i1], 1); g_eidx[i1*NT+pos1]=t;
    }
}

// ---------------- packed-f32x2 tiled SGEMM with fused epilogue + gather/scatter ----
// C[cm,N] (+)= rowscale[cm] * act( alpha * A[am]@B(^T) + bias[n] )
//   am = gatherA ? gidx[m] : m ;  cm = scatterC ? gidx[m] : m ; valid rows m < *gcount
// batched over blockIdx.z with offset = (z/hdiv)*s?o + (z%hdiv)*s?i
template<int BM,int BN,int TN>
__global__ void __launch_bounds__(256) gemm_t(
    const float* __restrict__ A, int lda, long long sAo, long long sAi,
    const float* __restrict__ Bm, int ldb, long long sBo, long long sBi, int transB,
    float* __restrict__ C, int ldc, long long sCo, long long sCi,
    int M, int N, int K, int hdiv,
    float alpha, const float* __restrict__ bias, int act,
    const float* __restrict__ rowscale, int rs_stride, int accum,
    const int* __restrict__ gidx, const int* __restrict__ gcount,
    int gatherA, int scatterC)
{
    constexpr int BK = 16;
    constexpr int TM = 8;
    constexpr int NTH = (BM/TM)*(BN/TN);
    static_assert(NTH == 256, "256 threads expected");

    int z = blockIdx.z;
    int zo = z / hdiv, zi = z - zo*hdiv;
    A  += zo*sAo + zi*sAi;
    Bm += zo*sBo + zi*sBi;
    C  += zo*sCo + zi*sCi;

    int count = gcount ? *gcount : M;
    int m0 = blockIdx.y * BM;
    int n0 = blockIdx.x * BN;
    if (m0 >= count) return;

    __shared__ float As[BK][BM];
    __shared__ float Bs[BK][BN];

    int tid = threadIdx.x;
    int tx = tid & 15;          // BN/TN == 16 for both variants
    int ty = tid >> 4;
    int row0 = ty*TM;
    int col0 = tx*TN;

    unsigned long long acc[TM][TN/2];
    #pragma unroll
    for (int i=0;i<TM;i++)
        #pragma unroll
        for (int jp=0;jp<TN/2;jp++) acc[i][jp]=0ULL;

    for (int k0 = 0; k0 < K; k0 += BK) {
        // load A tile (gathered, clamped rows)
        #pragma unroll
        for (int i = tid; i < BM*(BK/4); i += NTH) {
            int row = i >> 2;
            int kc  = (i & 3) * 4;
            int ar  = m0 + row;
            ar = ar < count ? ar : count-1;
            int arow = gatherA ? gidx[ar] : ar;
            float4 av = *(const float4*)(A + (long long)arow*lda + (k0 + kc));
            As[kc+0][row]=av.x; As[kc+1][row]=av.y; As[kc+2][row]=av.z; As[kc+3][row]=av.w;
        }
        // load B tile
        if (transB) {
            #pragma unroll
            for (int i = tid; i < BN*(BK/4); i += NTH) {
                int n  = i >> 2;
                int kc = (i & 3) * 4;
                float4 bv = *(const float4*)(Bm + (long long)(n0+n)*ldb + (k0+kc));
                Bs[kc+0][n]=bv.x; Bs[kc+1][n]=bv.y; Bs[kc+2][n]=bv.z; Bs[kc+3][n]=bv.w;
            }
        } else {
            #pragma unroll
            for (int i = tid; i < BK*(BN/4); i += NTH) {
                int kr = i / (BN/4);
                int n  = (i % (BN/4)) * 4;
                float4 bv = *(const float4*)(Bm + (long long)(k0+kr)*ldb + (n0+n));
                *(float4*)&Bs[kr][n] = bv;
            }
        }
        __syncthreads();
        #pragma unroll
        for (int kk=0;kk<BK;kk++){
            float av[TM];
            *(float4*)&av[0] = *(const float4*)&As[kk][row0];
            *(float4*)&av[4] = *(const float4*)&As[kk][row0+4];
            unsigned long long bd[TN/2];
            #pragma unroll
            for (int jp=0;jp<TN/2;jp++)
                bd[jp] = ((const unsigned long long*)&Bs[kk][col0])[jp];
            #pragma unroll
            for (int i=0;i<TM;i++){
                unsigned long long ad;
                DUP2(ad, av[i]);
                #pragma unroll
                for (int jp=0;jp<TN/2;jp++)
                    FMA2(acc[i][jp], ad, bd[jp], acc[i][jp]);
            }
        }
        __syncthreads();
    }

    #pragma unroll
    for (int i=0;i<TM;i++){
        int m = m0 + row0 + i;
        if (m < count) {
            int cm = scatterC ? gidx[m] : m;
            float rs = rowscale ? rowscale[(long long)cm*rs_stride] : 1.0f;
            #pragma unroll
            for (int jp=0;jp<TN/2;jp++){
                float v0, v1;
                UNP2(v0, v1, acc[i][jp]);
                int n = n0 + col0 + 2*jp;
                v0 *= alpha; v1 *= alpha;
                if (bias) { v0 += bias[n]; v1 += bias[n+1]; }
                if (act)  { v0 = gelu_f(v0); v1 = gelu_f(v1); }
                v0 *= rs; v1 *= rs;
                long long idx = (long long)cm*ldc + n;
                if (accum) { C[idx] += v0; C[idx+1] += v1; }
                else       { C[idx]  = v0; C[idx+1]  = v1; }
            }
        }
    }
}

struct GArg {
    const float*A; int lda; long long sAo,sAi;
    const float*B; int ldb; long long sBo,sBi; int transB;
    float*C; int ldc; long long sCo,sCi;
    int M,N,K,batch,hdiv;
    float alpha; const float*bias; int act;
    const float*rs; int rss; int accum;
    const int* gidx; const int* gcnt; int gA, sC;
};

template<int BM,int BN,int TN>
static void launch_g(const GArg& g){
    dim3 grid((unsigned)(g.N/BN), (unsigned)((g.M+BM-1)/BM), (unsigned)g.batch);
    gemm_t<BM,BN,TN><<<grid,256>>>(g.A,g.lda,g.sAo,g.sAi, g.B,g.ldb,g.sBo,g.sBi,g.transB,
        g.C,g.ldc,g.sCo,g.sCi, g.M,g.N,g.K,g.hdiv, g.alpha,g.bias,g.act,
        g.rs,g.rss,g.accum, g.gidx,g.gcnt,g.gA,g.sC);
}

extern "C" void kernel_launch(void* const* d_in, const int* in_sizes, int n_in,
                              void* d_out, int out_size)
{
    (void)in_sizes; (void)n_in; (void)out_size;
    const int*   text  = (const int*)  d_in[0];
    const float* embed = (const float*)d_in[1];
    const float* conv_w= (const float*)d_in[2];
    const float* conv_b= (const float*)d_in[3];
    const float* Wq    = (const float*)d_in[4];
    const float* bq    = (const float*)d_in[5];
    const float* Wk    = (const float*)d_in[6];
    const float* bk    = (const float*)d_in[7];
    const float* Wv    = (const float*)d_in[8];
    const float* bv    = (const float*)d_in[9];
    const float* Wo    = (const float*)d_in[10];
    const float* bo    = (const float*)d_in[11];
    const float* rw    = (const float*)d_in[12];
    const float* rb    = (const float*)d_in[13];
    const float* ew1   = (const float*)d_in[14];
    const float* eb1   = (const float*)d_in[15];
    const float* ew2   = (const float*)d_in[16];
    const float* eb2   = (const float*)d_in[17];
    const float* ln1g  = (const float*)d_in[18];
    const float* ln1b  = (const float*)d_in[19];
    const float* ln2g  = (const float*)d_in[20];
    const float* ln2b  = (const float*)d_in[21];
    const float* lnfg  = (const float*)d_in[22];
    const float* lnfb  = (const float*)d_in[23];
    const float* outw  = (const float*)d_in[24];
    const float* outb  = (const float*)d_in[25];
    float* out = (float*)d_out;

    float *x,*h,*q,*k,*v,*o,*sc,*xc,*wc,*h1,*gate;
    int *eidx,*ecnt;
    cudaGetSymbolAddress((void**)&x,  g_x);
    cudaGetSymbolAddress((void**)&h,  g_h);
    cudaGetSymbolAddress((void**)&q,  g_q);
    cudaGetSymbolAddress((void**)&k,  g_k);
    cudaGetSymbolAddress((void**)&v,  g_v);
    cudaGetSymbolAddress((void**)&o,  g_o);
    cudaGetSymbolAddress((void**)&sc, g_sc);
    cudaGetSymbolAddress((void**)&xc, g_xc);
    cudaGetSymbolAddress((void**)&wc, g_wc);
    cudaGetSymbolAddress((void**)&h1, g_h1);
    cudaGetSymbolAddress((void**)&gate, g_gate);
    cudaGetSymbolAddress((void**)&eidx, g_eidx);
    cudaGetSymbolAddress((void**)&ecnt, g_ecnt);

    // ---- tokenizer: embed + conv1d(SAME) + gelu + residual ----
    embed_kernel<<<NT,256>>>(text, embed);
    repack_conv_kernel<<<(3*ND*ND+255)/256,256>>>(conv_w);
    xcat_kernel<<<NT,256>>>();
    {   // x += gelu(xcat @ wc + conv_b)
        GArg g = {xc,3*ND,0,0, wc,ND,0,0,0, x,ND,0,0,
                  NT,ND,3*ND,1,1, 1.0f, conv_b, 1, nullptr,0, 1, nullptr,nullptr,0,0};
        launch_g<128,128,8>(g);
    }

    const long long sQK = (long long)NS*ND;   // per-batch stride in q/k/v/o
    const long long sSC = (long long)NS*NS;   // per-head stride in scores

    for (int i=0;i<NL;i++){
        // ---- attention ----
        ln_kernel<<<NT,256>>>(x, ln1g+(size_t)i*ND, ln1b+(size_t)i*ND, h);
        {   GArg g = {h,ND,0,0, Wq+(size_t)i*ND*ND,ND,0,0,0, q,ND,0,0,
                      NT,ND,ND,1,1, 1.0f, bq+(size_t)i*ND, 0, nullptr,0, 0, nullptr,nullptr,0,0};
            launch_g<128,128,8>(g); }
        {   GArg g = {h,ND,0,0, Wk+(size_t)i*ND*ND,ND,0,0,0, k,ND,0,0,
                      NT,ND,ND,1,1, 1.0f, bk+(size_t)i*ND, 0, nullptr,0, 0, nullptr,nullptr,0,0};
            launch_g<128,128,8>(g); }
        {   GArg g = {h,ND,0,0, Wv+(size_t)i*ND*ND,ND,0,0,0, v,ND,0,0,
                      NT,ND,ND,1,1, 1.0f, bv+(size_t)i*ND, 0, nullptr,0, 0, nullptr,nullptr,0,0};
            launch_g<128,128,8>(g); }
        // scores[b,h] = 0.125 * Q_bh @ K_bh^T
        {   GArg g = {q,ND,sQK,NDH, k,ND,sQK,NDH,1, sc,NS,(long long)NH*sSC,sSC,
                      NS,NS,NDH,NB*NH,NH, 0.125f, nullptr,0, nullptr,0, 0, nullptr,nullptr,0,0};
            launch_g<128,128,8>(g); }
        softmax_kernel<<<NB*NH*NS,256>>>();
        // O_bh = A_bh @ V_bh   (N=64 -> narrow variant)
        {   GArg g = {sc,NS,(long long)NH*sSC,sSC, v,ND,sQK,NDH,0, o,ND,sQK,NDH,
                      NS,NDH,NS,NB*NH,NH, 1.0f, nullptr,0, nullptr,0, 0, nullptr,nullptr,0,0};
            launch_g<128,64,4>(g); }
        // x += o @ Wo + bo
        {   GArg g = {o,ND,0,0, Wo+(size_t)i*ND*ND,ND,0,0,0, x,ND,0,0,
                      NT,ND,ND,1,1, 1.0f, bo+(size_t)i*ND, 0, nullptr,0, 1, nullptr,nullptr,0,0};
            launch_g<128,128,8>(g); }

        // ---- MoE (top-2 gathered) ----
        ln_kernel<<<NT,256>>>(x, ln2g+(size_t)i*ND, ln2b+(size_t)i*ND, h);
        zero_cnt_kernel<<<1,32>>>();
        router_kernel<<<NT/4, dim3(32,4)>>>(h, rw+(size_t)i*ND*NE, rb+(size_t)i*NE);
        for (int e=0;e<NE;e++){
            const float* w1 = ew1 + ((size_t)(i*NE+e))*ND*NF;
            const float* b1 = eb1 + ((size_t)(i*NE+e))*NF;
            const float* w2 = ew2 + ((size_t)(i*NE+e))*NF*ND;
            const float* b2 = eb2 + ((size_t)(i*NE+e))*ND;
            // h1[0:cnt] = gelu(h[idx] @ w1 + b1)       (gather A)
            {   GArg g = {h,ND,0,0, w1,NF,0,0,0, h1,NF,0,0,
                          NT,NF,ND,1,1, 1.0f, b1, 1, nullptr,0, 0,
                          eidx+(size_t)e*NT, ecnt+e, 1, 0};
                launch_g<128,128,8>(g); }
            // x[idx] += gate[idx,e] * (h1[0:cnt] @ w2 + b2)   (scatter C)
            {   GArg g = {h1,NF,0,0, w2,ND,0,0,0, x,ND,0,0,
                          NT,ND,NF,1,1, 1.0f, b2, 0, gate+e, NE, 1,
                          eidx+(size_t)e*NT, ecnt+e, 0, 1};
                launch_g<128,128,8>(g); }
        }
    }

    // ---- final LN + output projection ----
    ln_kernel<<<NT,256>>>(x, lnfg, lnfb, h);
    {   GArg g = {h,ND,0,0, outw,NV,0,0,0, out,NV,0,0,
                  NT,NV,ND,1,1, 1.0f, outb, 0, nullptr,0, 0, nullptr,nullptr,0,0};
        launch_g<128,128,8>(g); }
}

// round 3
// speedup vs baseline: 1.8856x; 1.4987x over previous
#include <cuda_runtime.h>
#include <math.h>

#define NL 4
#define NB 4
#define NS 1024
#define ND 768
#define NF 3072
#define NE 4
#define NV 256
#define NH 12
#define NDH 64
#define NT (NB*NS)

// ---------------- packed f32x2 helpers (ptxas never emits these from C++) ----------
#define FMA2(d,a,b,c) asm("fma.rn.f32x2 %0, %1, %2, %3;" : "=l"(d) : "l"(a), "l"(b), "l"(c))
#define DUP2(d,s)     asm("mov.b64 %0, {%1, %1};" : "=l"(d) : "f"(s))
#define UNP2(lo,hi,v) asm("mov.b64 {%0, %1}, %2;" : "=f"(lo), "=f"(hi) : "l"(v))

// ---------------- scratch (device globals; no allocation allowed) ----------------
__device__ float g_x[NT*ND];
__device__ float g_h[NT*ND];
__device__ float g_q[NT*ND];
__device__ float g_k[NT*ND];
__device__ float g_v[NT*ND];
__device__ float g_o[NT*ND];
__device__ float g_sc[(size_t)NB*NH*NS*NS];   // attention scores
__device__ float g_xc[NT*3*ND];               // im2col for conv
__device__ float g_wc[3*ND*ND];               // repacked conv weight [3D, D]
__device__ float g_h1[NT*NF];                 // expert hidden (compacted per expert)
__device__ float g_gate[NT*NE];               // top-2 renormalized gates
__device__ int   g_eidx[NE*NT];               // per-expert compacted token lists
__device__ int   g_ecnt[NE];                  // per-expert token counts

__device__ __forceinline__ float gelu_f(float x){
    const float c = 0.7978845608028654f;
    return 0.5f*x*(1.0f + tanhf(c*(x + 0.044715f*x*x*x)));
}

// ---------------- embedding lookup ----------------
__global__ void embed_kernel(const int* __restrict__ text, const float* __restrict__ emb){
    int t = blockIdx.x;
    int tok = text[t];
    const float* src = emb + (size_t)tok*ND;
    float* dst = g_x + (size_t)t*ND;
    for (int d = threadIdx.x; d < ND; d += blockDim.x) dst[d] = src[d];
}

__global__ void repack_conv_kernel(const float* __restrict__ w){
    int idx = blockIdx.x*blockDim.x + threadIdx.x;
    if (idx >= 3*ND*ND) return;
    int o = idx % ND;
    int r = idx / ND;
    int i = r % ND;
    int k = r / ND;
    g_wc[idx] = w[((size_t)o*ND + i)*3 + k];
}

__global__ void xcat_kernel(){
    int t = blockIdx.x;
    int s = t % NS;
    float* dst = g_xc + (size_t)t*3*ND;
    for (int idx = threadIdx.x; idx < 3*ND; idx += blockDim.x) {
        int k = idx / ND, i = idx % ND;
        int sp = s + k - 1;
        dst[idx] = (sp >= 0 && sp < NS) ? g_x[(size_t)(t + k - 1)*ND + i] : 0.0f;
    }
}

// ---------------- layernorm ----------------
__global__ void ln_kernel(const float* __restrict__ x, const float* __restrict__ g,
                          const float* __restrict__ b, float* __restrict__ out){
    __shared__ float red[256];
    int r = blockIdx.x;
    const float* xr = x + (size_t)r*ND;
    int tid = threadIdx.x;
    float s = 0.f;
    for (int d = tid; d < ND; d += 256) s += xr[d];
    red[tid] = s; __syncthreads();
    for (int o = 128; o > 0; o >>= 1){ if (tid < o) red[tid] += red[tid+o]; __syncthreads(); }
    float mean = red[0] / (float)ND;
    __syncthreads();
    float vs = 0.f;
    for (int d = tid; d < ND; d += 256){ float dd = xr[d]-mean; vs += dd*dd; }
    red[tid] = vs; __syncthreads();
    for (int o = 128; o > 0; o >>= 1){ if (tid < o) red[tid] += red[tid+o]; __syncthreads(); }
    float rstd = rsqrtf(red[0]/(float)ND + 1e-5f);
    float* orow = out + (size_t)r*ND;
    for (int d = tid; d < ND; d += 256)
        orow[d] = (xr[d]-mean)*rstd*g[d] + b[d];
}

// ---------------- row softmax over S=1024 ----------------
__global__ void softmax_kernel(){
    __shared__ float red[256];
    size_t row = blockIdx.x;
    float* p = g_sc + row*(size_t)NS;
    int tid = threadIdx.x;
    float m = -1e30f;
    for (int d = tid; d < NS; d += 256) m = fmaxf(m, p[d]);
    red[tid]=m; __syncthreads();
    for (int o=128;o>0;o>>=1){ if(tid<o) red[tid]=fmaxf(red[tid],red[tid+o]); __syncthreads(); }
    m = red[0]; __syncthreads();
    float s=0.f;
    for (int d = tid; d < NS; d += 256){ float e = expf(p[d]-m); p[d]=e; s+=e; }
    red[tid]=s; __syncthreads();
    for (int o=128;o>0;o>>=1){ if(tid<o) red[tid]+=red[tid+o]; __syncthreads(); }
    float inv = 1.0f/red[0];
    for (int d = tid; d < NS; d += 256) p[d] *= inv;
}

__global__ void zero_cnt_kernel(){
    if (threadIdx.x < NE) g_ecnt[threadIdx.x] = 0;
}

// ---------------- router: softmax -> top2 -> gates + compacted expert lists ------
__global__ void router_kernel(const float* __restrict__ h, const float* __restrict__ rw,
                              const float* __restrict__ rb){
    int t = blockIdx.x*blockDim.y + threadIdx.y;
    int lane = threadIdx.x;
    float a0=0.f,a1=0.f,a2=0.f,a3=0.f;
    const float* hr = h + (size_t)t*ND;
    for (int d = lane; d < ND; d += 32){
        float hv = hr[d];
        a0 += hv*rw[d*NE+0];
        a1 += hv*rw[d*NE+1];
        a2 += hv*rw[d*NE+2];
        a3 += hv*rw[d*NE+3];
    }
    #pragma unroll
    for (int o=16;o>0;o>>=1){
        a0 += __shfl_down_sync(0xffffffffu, a0, o);
        a1 += __shfl_down_sync(0xffffffffu, a1, o);
        a2 += __shfl_down_sync(0xffffffffu, a2, o);
        a3 += __shfl_down_sync(0xffffffffu, a3, o);
    }
    if (lane==0){
        float l[4]={a0+rb[0],a1+rb[1],a2+rb[2],a3+rb[3]};
        float lm = fmaxf(fmaxf(l[0],l[1]),fmaxf(l[2],l[3]));
        float p[4]; float sum=0.f;
        #pragma unroll
        for(int e=0;e<4;e++){ p[e]=expf(l[e]-lm); sum+=p[e]; }
        #pragma unroll
        for(int e=0;e<4;e++) p[e]/=sum;
        int i0=0;
        #pragma unroll
        for(int e=1;e<4;e++) if(p[e]>p[i0]) i0=e;
        int i1=-1;
        #pragma unroll
        for(int e=0;e<4;e++){ if(e==i0) continue; if(i1<0 || p[e]>p[i1]) i1=e; }
        float gs = p[i0]+p[i1];
        float outv[4]={0.f,0.f,0.f,0.f};
        outv[i0]=p[i0]/gs; outv[i1]=p[i1]/gs;
        #pragma unroll
        for(int e=0;e<4;e++) g_gate[(size_t)t*NE+e]=outv[e];
        int pos0 = atomicAdd(&g_ecnt[i0], 1); g_eidx[i0*NT+pos0]=t;
        int pos1 = atomicAdd(&g_ecnt[i1], 1); g_eidx[i1*NT+pos1]=t;
    }
}

// ---------------- pipelined packed-f32x2 SGEMM, double-buffered smem --------------
// C[cm,N] (+)= rowscale[cm] * act( alpha * A[am]@B(^T) + bias[n] )
template<int BM,int BN,int TN>
__global__ void __launch_bounds__(256,2) gemm_t(
    const float* __restrict__ A, int lda, long long sAo, long long sAi,
    const float* __restrict__ Bm, int ldb, long long sBo, long long sBi, int transB,
    float* __restrict__ C, int ldc, long long sCo, long long sCi,
    int M, int N, int K, int hdiv,
    float alpha, const float* __restrict__ bias, int act,
    const float* __restrict__ rowscale, int rs_stride, int accum,
    const int* __restrict__ gidx, const int* __restrict__ gcount,
    int gatherA, int scatterC)
{
    constexpr int BK = 16;
    constexpr int TM = 8;
    constexpr int NTH = 256;
    constexpr int NA  = BM*BK/(4*NTH);   // float4 A-loads per thread (2)
    constexpr int NBt = BN*BK/(4*NTH);   // float4 B-loads per thread (2 or 1)
    static_assert((BM/TM)*(BN/TN) == NTH, "bad tiling");

    int z = blockIdx.z;
    int zo = z / hdiv, zi = z - zo*hdiv;
    A  += zo*sAo + zi*sAi;
    Bm += zo*sBo + zi*sBi;
    C  += zo*sCo + zi*sCi;

    int count = gcount ? *gcount : M;
    int m0 = blockIdx.y * BM;
    int n0 = blockIdx.x * BN;
    if (m0 >= count) return;

    __shared__ float As[2][BK][BM+4];
    __shared__ float Bs[2][BK][BN+4];

    int tid = threadIdx.x;
    int tx = tid & 15;
    int ty = tid >> 4;
    int row0 = ty*TM;
    int col0 = tx*TN;

    unsigned long long acc[TM][TN/2];
    #pragma unroll
    for (int i=0;i<TM;i++)
        #pragma unroll
        for (int jp=0;jp<TN/2;jp++) acc[i][jp]=0ULL;

    float4 sa[NA], sb[NBt];

    // --- staged global loads ---
    auto ldg_tile = [&](int k0){
        #pragma unroll
        for (int u=0;u<NA;u++){
            int i = tid + u*NTH;
            int row = i >> 2;
            int kc  = (i & 3) * 4;
            int ar  = m0 + row;
            ar = ar < count ? ar : count-1;
            int arow = gatherA ? gidx[ar] : ar;
            sa[u] = *(const float4*)(A + (long long)arow*lda + (k0 + kc));
        }
        if (transB) {
            #pragma unroll
            for (int u=0;u<NBt;u++){
                int i = tid + u*NTH;
                int n  = i >> 2;
                int kc = (i & 3) * 4;
                sb[u] = *(const float4*)(Bm + (long long)(n0+n)*ldb + (k0+kc));
            }
        } else {
            #pragma unroll
            for (int u=0;u<NBt;u++){
                int i = tid + u*NTH;
                int kr = i / (BN/4);
                int n  = (i % (BN/4)) * 4;
                sb[u] = *(const float4*)(Bm + (long long)(k0+kr)*ldb + (n0+n));
            }
        }
    };
    auto sts_tile = [&](int buf){
        #pragma unroll
        for (int u=0;u<NA;u++){
            int i = tid + u*NTH;
            int row = i >> 2;
            int kc  = (i & 3) * 4;
            As[buf][kc+0][row]=sa[u].x; As[buf][kc+1][row]=sa[u].y;
            As[buf][kc+2][row]=sa[u].z; As[buf][kc+3][row]=sa[u].w;
        }
        if (transB) {
            #pragma unroll
            for (int u=0;u<NBt;u++){
                int i = tid + u*NTH;
                int n  = i >> 2;
                int kc = (i & 3) * 4;
                Bs[buf][kc+0][n]=sb[u].x; Bs[buf][kc+1][n]=sb[u].y;
                Bs[buf][kc+2][n]=sb[u].z; Bs[buf][kc+3][n]=sb[u].w;
            }
        } else {
            #pragma unroll
            for (int u=0;u<NBt;u++){
                int i = tid + u*NTH;
                int kr = i / (BN/4);
                int n  = (i % (BN/4)) * 4;
                *(float4*)&Bs[buf][kr][n] = sb[u];
            }
        }
    };

    ldg_tile(0);
    sts_tile(0);
    __syncthreads();

    int buf = 0;
    for (int k0 = 0; k0 < K; k0 += BK) {
        bool has_next = (k0 + BK) < K;
        if (has_next) ldg_tile(k0 + BK);

        #pragma unroll
        for (int kk=0;kk<BK;kk++){
            float av[TM];
            *(float4*)&av[0] = *(const float4*)&As[buf][kk][row0];
            *(float4*)&av[4] = *(const float4*)&As[buf][kk][row0+4];
            unsigned long long bd[TN/2];
            #pragma unroll
            for (int jp=0;jp<TN/2;jp++)
                bd[jp] = *(const unsigned long long*)&Bs[buf][kk][col0+2*jp];
            #pragma unroll
            for (int i=0;i<TM;i++){
                unsigned long long ad;
                DUP2(ad, av[i]);
                #pragma unroll
                for (int jp=0;jp<TN/2;jp++)
                    FMA2(acc[i][jp], ad, bd[jp], acc[i][jp]);
            }
        }

        if (has_next) {
            sts_tile(buf ^ 1);
            __syncthreads();
            buf ^= 1;
        }
    }

    #pragma unroll
    for (int i=0;i<TM;i++){
        int m = m0 + row0 + i;
        if (m < count) {
            int cm = scatterC ? gidx[m] : m;
            float rs = rowscale ? rowscale[(long long)cm*rs_stride] : 1.0f;
            #pragma unroll
            for (int jp=0;jp<TN/2;jp++){
                float v0, v1;
                UNP2(v0, v1, acc[i][jp]);
                int n = n0 + col0 + 2*jp;
                v0 *= alpha; v1 *= alpha;
                if (bias) { v0 += bias[n]; v1 += bias[n+1]; }
                if (act)  { v0 = gelu_f(v0); v1 = gelu_f(v1); }
                v0 *= rs; v1 *= rs;
                long long idx = (long long)cm*ldc + n;
                if (accum) { C[idx] += v0; C[idx+1] += v1; }
                else       { C[idx]  = v0; C[idx+1]  = v1; }
            }
        }
    }
}

struct GArg {
    const float*A; int lda; long long sAo,sAi;
    const float*B; int ldb; long long sBo,sBi; int transB;
    float*C; int ldc; long long sCo,sCi;
    int M,N,K,batch,hdiv;
    float alpha; const float*bias; int act;
    const float*rs; int rss; int accum;
    const int* gidx; const int* gcnt; int gA, sC;
};

template<int BM,int BN,int TN>
static void launch_g(const GArg& g){
    dim3 grid((unsigned)(g.N/BN), (unsigned)((g.M+BM-1)/BM), (unsigned)g.batch);
    gemm_t<BM,BN,TN><<<grid,256>>>(g.A,g.lda,g.sAo,g.sAi, g.B,g.ldb,g.sBo,g.sBi,g.transB,
        g.C,g.ldc,g.sCo,g.sCi, g.M,g.N,g.K,g.hdiv, g.alpha,g.bias,g.act,
        g.rs,g.rss,g.accum, g.gidx,g.gcnt,g.gA,g.sC);
}

extern "C" void kernel_launch(void* const* d_in, const int* in_sizes, int n_in,
                              void* d_out, int out_size)
{
    (void)in_sizes; (void)n_in; (void)out_size;
    const int*   text  = (const int*)  d_in[0];
    const float* embed = (const float*)d_in[1];
    const float* conv_w= (const float*)d_in[2];
    const float* conv_b= (const float*)d_in[3];
    const float* Wq    = (const float*)d_in[4];
    const float* bq    = (const float*)d_in[5];
    const float* Wk    = (const float*)d_in[6];
    const float* bk    = (const float*)d_in[7];
    const float* Wv    = (const float*)d_in[8];
    const float* bv    = (const float*)d_in[9];
    const float* Wo    = (const float*)d_in[10];
    const float* bo    = (const float*)d_in[11];
    const float* rw    = (const float*)d_in[12];
    const float* rb    = (const float*)d_in[13];
    const float* ew1   = (const float*)d_in[14];
    const float* eb1   = (const float*)d_in[15];
    const float* ew2   = (const float*)d_in[16];
    const float* eb2   = (const float*)d_in[17];
    const float* ln1g  = (const float*)d_in[18];
    const float* ln1b  = (const float*)d_in[19];
    const float* ln2g  = (const float*)d_in[20];
    const float* ln2b  = (const float*)d_in[21];
    const float* lnfg  = (const float*)d_in[22];
    const float* lnfb  = (const float*)d_in[23];
    const float* outw  = (const float*)d_in[24];
    const float* outb  = (const float*)d_in[25];
    float* out = (float*)d_out;

    float *x,*h,*q,*k,*v,*o,*sc,*xc,*wc,*h1,*gate;
    int *eidx,*ecnt;
    cudaGetSymbolAddress((void**)&x,  g_x);
    cudaGetSymbolAddress((void**)&h,  g_h);
    cudaGetSymbolAddress((void**)&q,  g_q);
    cudaGetSymbolAddress((void**)&k,  g_k);
    cudaGetSymbolAddress((void**)&v,  g_v);
    cudaGetSymbolAddress((void**)&o,  g_o);
    cudaGetSymbolAddress((void**)&sc, g_sc);
    cudaGetSymbolAddress((void**)&xc, g_xc);
    cudaGetSymbolAddress((void**)&wc, g_wc);
    cudaGetSymbolAddress((void**)&h1, g_h1);
    cudaGetSymbolAddress((void**)&gate, g_gate);
    cudaGetSymbolAddress((void**)&eidx, g_eidx);
    cudaGetSymbolAddress((void**)&ecnt, g_ecnt);

    // ---- tokenizer: embed + conv1d(SAME) + gelu + residual ----
    embed_kernel<<<NT,256>>>(text, embed);
    repack_conv_kernel<<<(3*ND*ND+255)/256,256>>>(conv_w);
    xcat_kernel<<<NT,256>>>();
    {   GArg g = {xc,3*ND,0,0, wc,ND,0,0,0, x,ND,0,0,
                  NT,ND,3*ND,1,1, 1.0f, conv_b, 1, nullptr,0, 1, nullptr,nullptr,0,0};
        launch_g<128,64,4>(g);
    }

    const long long sQK = (long long)NS*ND;
    const long long sSC = (long long)NS*NS;

    for (int i=0;i<NL;i++){
        // ---- attention ----
        ln_kernel<<<NT,256>>>(x, ln1g+(size_t)i*ND, ln1b+(size_t)i*ND, h);
        {   GArg g = {h,ND,0,0, Wq+(size_t)i*ND*ND,ND,0,0,0, q,ND,0,0,
                      NT,ND,ND,1,1, 1.0f, bq+(size_t)i*ND, 0, nullptr,0, 0, nullptr,nullptr,0,0};
            launch_g<128,64,4>(g); }
        {   GArg g = {h,ND,0,0, Wk+(size_t)i*ND*ND,ND,0,0,0, k,ND,0,0,
                      NT,ND,ND,1,1, 1.0f, bk+(size_t)i*ND, 0, nullptr,0, 0, nullptr,nullptr,0,0};
            launch_g<128,64,4>(g); }
        {   GArg g = {h,ND,0,0, Wv+(size_t)i*ND*ND,ND,0,0,0, v,ND,0,0,
                      NT,ND,ND,1,1, 1.0f, bv+(size_t)i*ND, 0, nullptr,0, 0, nullptr,nullptr,0,0};
            launch_g<128,64,4>(g); }
        // scores[b,h] = 0.125 * Q_bh @ K_bh^T
        {   GArg g = {q,ND,sQK,NDH, k,ND,sQK,NDH,1, sc,NS,(long long)NH*sSC,sSC,
                      NS,NS,NDH,NB*NH,NH, 0.125f, nullptr,0, nullptr,0, 0, nullptr,nullptr,0,0};
            launch_g<128,128,8>(g); }
        softmax_kernel<<<NB*NH*NS,256>>>();
        // O_bh = A_bh @ V_bh
        {   GArg g = {sc,NS,(long long)NH*sSC,sSC, v,ND,sQK,NDH,0, o,ND,sQK,NDH,
                      NS,NDH,NS,NB*NH,NH, 1.0f, nullptr,0, nullptr,0, 0, nullptr,nullptr,0,0};
            launch_g<128,64,4>(g); }
        // x += o @ Wo + bo
        {   GArg g = {o,ND,0,0, Wo+(size_t)i*ND*ND,ND,0,0,0, x,ND,0,0,
                      NT,ND,ND,1,1, 1.0f, bo+(size_t)i*ND, 0, nullptr,0, 1, nullptr,nullptr,0,0};
            launch_g<128,64,4>(g); }

        // ---- MoE (top-2 gathered) ----
        ln_kernel<<<NT,256>>>(x, ln2g+(size_t)i*ND, ln2b+(size_t)i*ND, h);
        zero_cnt_kernel<<<1,32>>>();
        router_kernel<<<NT/4, dim3(32,4)>>>(h, rw+(size_t)i*ND*NE, rb+(size_t)i*NE);
        for (int e=0;e<NE;e++){
            const float* w1 = ew1 + ((size_t)(i*NE+e))*ND*NF;
            const float* b1 = eb1 + ((size_t)(i*NE+e))*NF;
            const float* w2 = ew2 + ((size_t)(i*NE+e))*NF*ND;
            const float* b2 = eb2 + ((size_t)(i*NE+e))*ND;
            // h1[0:cnt] = gelu(h[idx] @ w1 + b1)       (gather A)
            {   GArg g = {h,ND,0,0, w1,NF,0,0,0, h1,NF,0,0,
                          NT,NF,ND,1,1, 1.0f, b1, 1, nullptr,0, 0,
                          eidx+(size_t)e*NT, ecnt+e, 1, 0};
                launch_g<128,128,8>(g); }
            // x[idx] += gate[idx,e] * (h1[0:cnt] @ w2 + b2)   (scatter C)
            {   GArg g = {h1,NF,0,0, w2,ND,0,0,0, x,ND,0,0,
                          NT,ND,NF,1,1, 1.0f, b2, 0, gate+e, NE, 1,
                          eidx+(size_t)e*NT, ecnt+e, 0, 1};
                launch_g<128,64,4>(g); }
        }
    }

    // ---- final LN + output projection ----
    ln_kernel<<<NT,256>>>(x, lnfg, lnfb, h);
    {   GArg g = {h,ND,0,0, outw,NV,0,0,0, out,NV,0,0,
                  NT,NV,ND,1,1, 1.0f, outb, 0, nullptr,0, 0, nullptr,nullptr,0,0};
        launch_g<128,64,4>(g); }
}

// round 5
// speedup vs baseline: 2.7613x; 1.4644x over previous
#include <cuda_runtime.h>
#include <cuda_bf16.h>
#include <math.h>
#include <stdint.h>

#define NL 4
#define NB 4
#define NS 1024
#define ND 768
#define NF 3072
#define NE 4
#define NV 256
#define NH 12
#define NDH 64
#define NT (NB*NS)

// ================= packed f32x2 helpers (attention SGEMM) =================
#define FMA2(d,a,b,c) asm("fma.rn.f32x2 %0, %1, %2, %3;" : "=l"(d) : "l"(a), "l"(b), "l"(c))
#define DUP2(d,s)     asm("mov.b64 %0, {%1, %1};" : "=l"(d) : "f"(s))
#define UNP2(lo,hi,v) asm("mov.b64 {%0, %1}, %2;" : "=f"(lo), "=f"(hi) : "l"(v))

__device__ __forceinline__ uint32_t smem_u32(const void* p){
    uint32_t a;
    asm("{ .reg .u64 t; cvta.to.shared.u64 t, %1; cvt.u32.u64 %0, t; }" : "=r"(a) : "l"(p));
    return a;
}

// ldmatrix wrappers (sm_80+, fine on compute_103)
#define LDSM_X4(r0,r1,r2,r3,addr) \
    asm volatile("ldmatrix.sync.aligned.m8n8.x4.shared.b16 {%0,%1,%2,%3}, [%4];" \
        : "=r"(r0),"=r"(r1),"=r"(r2),"=r"(r3) : "r"(addr))
#define LDSM_X2(r0,r1,addr) \
    asm volatile("ldmatrix.sync.aligned.m8n8.x2.shared.b16 {%0,%1}, [%2];" \
        : "=r"(r0),"=r"(r1) : "r"(addr))
#define MMA16816(d,a,b) \
    asm volatile("mma.sync.aligned.m16n8k16.row.col.f32.bf16.bf16.f32 " \
        "{%0,%1,%2,%3}, {%4,%5,%6,%7}, {%8,%9}, {%0,%1,%2,%3};" \
        : "+f"((d)[0]),"+f"((d)[1]),"+f"((d)[2]),"+f"((d)[3]) \
        : "r"((a)[0]),"r"((a)[1]),"r"((a)[2]),"r"((a)[3]), "r"((b)[0]),"r"((b)[1]))

// ================= scratch =================
__device__ float g_x[NT*ND];
__device__ float g_h[NT*ND];
__device__ float g_q[NT*ND];
__device__ float g_k[NT*ND];
__device__ float g_v[NT*ND];
__device__ float g_o[NT*ND];
__device__ float g_sc[(size_t)NB*NH*NS*NS];
__device__ float g_gate[NT*NE];
__device__ int   g_eidx[NE*NT];
__device__ int   g_ecnt[NE];

__device__ __nv_bfloat16 g_hb_h[NT*ND],  g_hb_l[NT*ND];
__device__ __nv_bfloat16 g_ob_h[NT*ND],  g_ob_l[NT*ND];
__device__ __nv_bfloat16 g_xcb_h[NT*3*ND], g_xcb_l[NT*3*ND];
__device__ __nv_bfloat16 g_h1b_h[NT*NF], g_h1b_l[NT*NF];
__device__ __nv_bfloat16 g_wcT_h[ND*3*ND], g_wcT_l[ND*3*ND];
__device__ __nv_bfloat16 g_wqT_h[NL*ND*ND], g_wqT_l[NL*ND*ND];
__device__ __nv_bfloat16 g_wkT_h[NL*ND*ND], g_wkT_l[NL*ND*ND];
__device__ __nv_bfloat16 g_wvT_h[NL*ND*ND], g_wvT_l[NL*ND*ND];
__device__ __nv_bfloat16 g_woT_h[NL*ND*ND], g_woT_l[NL*ND*ND];
__device__ __nv_bfloat16 g_w1T_h[NL*NE*NF*ND], g_w1T_l[NL*NE*NF*ND];
__device__ __nv_bfloat16 g_w2T_h[NL*NE*ND*NF], g_w2T_l[NL*NE*ND*NF];
__device__ __nv_bfloat16 g_woutT_h[NV*ND], g_woutT_l[NV*ND];

__device__ __forceinline__ float gelu_f(float x){
    const float c = 0.7978845608028654f;
    return 0.5f*x*(1.0f + tanhf(c*(x + 0.044715f*x*x*x)));
}
__device__ __forceinline__ void split_bf(float v, __nv_bfloat16& h, __nv_bfloat16& l){
    h = __float2bfloat16(v);
    l = __float2bfloat16(v - __bfloat162float(h));
}

// ================= small kernels =================
__global__ void embed_kernel(const int* __restrict__ text, const float* __restrict__ emb){
    int t = blockIdx.x;
    int tok = text[t];
    const float* src = emb + (size_t)tok*ND;
    float* dst = g_x + (size_t)t*ND;
    for (int d = threadIdx.x; d < ND; d += blockDim.x) dst[d] = src[d];
}

__global__ void convw_kernel(const float* __restrict__ w){
    int idx = blockIdx.x*blockDim.x + threadIdx.x;
    if (idx >= ND*3*ND) return;
    int o = idx / (3*ND);
    int r = idx % (3*ND);
    int k = r / ND, i = r % ND;
    float v = w[((size_t)o*ND + i)*3 + k];
    split_bf(v, g_wcT_h[idx], g_wcT_l[idx]);
}

__global__ void wtrans_kernel(const float* __restrict__ in, __nv_bfloat16* __restrict__ hi,
                              __nv_bfloat16* __restrict__ lo, int K, int N){
    __shared__ float t[32][33];
    size_t zo = (size_t)blockIdx.z*K*N;
    int n0 = blockIdx.x*32, k0 = blockIdx.y*32;
    int tx = threadIdx.x, ty = threadIdx.y;
    #pragma unroll
    for (int j=0;j<32;j+=8)
        t[ty+j][tx] = in[zo + (size_t)(k0+ty+j)*N + (n0+tx)];
    __syncthreads();
    #pragma unroll
    for (int j=0;j<32;j+=8){
        float v = t[tx][ty+j];
        size_t oi = zo + (size_t)(n0+ty+j)*K + (k0+tx);
        __nv_bfloat16 h,l; split_bf(v,h,l);
        hi[oi]=h; lo[oi]=l;
    }
}

__global__ void tobf_kernel(const float* __restrict__ in, __nv_bfloat16* __restrict__ hi,
                            __nv_bfloat16* __restrict__ lo, int n){
    int i = blockIdx.x*blockDim.x + threadIdx.x;
    if (i < n){ __nv_bfloat16 h,l; split_bf(in[i],h,l); hi[i]=h; lo[i]=l; }
}

__global__ void xcat_kernel(){
    int t = blockIdx.x;
    int s = t % NS;
    size_t base = (size_t)t*3*ND;
    for (int idx = threadIdx.x; idx < 3*ND; idx += blockDim.x) {
        int k = idx / ND, i = idx % ND;
        int sp = s + k - 1;
        float val = (sp >= 0 && sp < NS) ? g_x[(size_t)(t + k - 1)*ND + i] : 0.0f;
        __nv_bfloat16 h,l; split_bf(val,h,l);
        g_xcb_h[base+idx]=h; g_xcb_l[base+idx]=l;
    }
}

__global__ void ln_kernel(const float* __restrict__ x, const float* __restrict__ g,
                          const float* __restrict__ b, float* __restrict__ out,
                          __nv_bfloat16* __restrict__ oh, __nv_bfloat16* __restrict__ ol){
    __shared__ float red[256];
    int r = blockIdx.x;
    const float* xr = x + (size_t)r*ND;
    int tid = threadIdx.x;
    float s = 0.f;
    for (int d = tid; d < ND; d += 256) s += xr[d];
    red[tid] = s; __syncthreads();
    for (int o = 128; o > 0; o >>= 1){ if (tid < o) red[tid] += red[tid+o]; __syncthreads(); }
    float mean = red[0] / (float)ND;
    __syncthreads();
    float vs = 0.f;
    for (int d = tid; d < ND; d += 256){ float dd = xr[d]-mean; vs += dd*dd; }
    red[tid] = vs; __syncthreads();
    for (int o = 128; o > 0; o >>= 1){ if (tid < o) red[tid] += red[tid+o]; __syncthreads(); }
    float rstd = rsqrtf(red[0]/(float)ND + 1e-5f);
    size_t base = (size_t)r*ND;
    for (int d = tid; d < ND; d += 256){
        float v = (xr[d]-mean)*rstd*g[d] + b[d];
        out[base+d] = v;
        __nv_bfloat16 h,l; split_bf(v,h,l);
        oh[base+d]=h; ol[base+d]=l;
    }
}

__global__ void softmax_kernel(){
    __shared__ float red[256];
    size_t row = blockIdx.x;
    float* p = g_sc + row*(size_t)NS;
    int tid = threadIdx.x;
    float m = -1e30f;
    for (int d = tid; d < NS; d += 256) m = fmaxf(m, p[d]);
    red[tid]=m; __syncthreads();
    for (int o=128;o>0;o>>=1){ if(tid<o) red[tid]=fmaxf(red[tid],red[tid+o]); __syncthreads(); }
    m = red[0]; __syncthreads();
    float s=0.f;
    for (int d = tid; d < NS; d += 256){ float e = expf(p[d]-m); p[d]=e; s+=e; }
    red[tid]=s; __syncthreads();
    for (int o=128;o>0;o>>=1){ if(tid<o) red[tid]+=red[tid+o]; __syncthreads(); }
    float inv = 1.0f/red[0];
    for (int d = tid; d < NS; d += 256) p[d] *= inv;
}

__global__ void zero_cnt_kernel(){
    if (threadIdx.x < NE) g_ecnt[threadIdx.x] = 0;
}

__global__ void router_kernel(const float* __restrict__ h, const float* __restrict__ rw,
                              const float* __restrict__ rb){
    int t = blockIdx.x*blockDim.y + threadIdx.y;
    int lane = threadIdx.x;
    float a0=0.f,a1=0.f,a2=0.f,a3=0.f;
    const float* hr = h + (size_t)t*ND;
    for (int d = lane; d < ND; d += 32){
        float hv = hr[d];
        a0 += hv*rw[d*NE+0];
        a1 += hv*rw[d*NE+1];
        a2 += hv*rw[d*NE+2];
        a3 += hv*rw[d*NE+3];
    }
    #pragma unroll
    for (int o=16;o>0;o>>=1){
        a0 += __shfl_down_sync(0xffffffffu, a0, o);
        a1 += __shfl_down_sync(0xffffffffu, a1, o);
        a2 += __shfl_down_sync(0xffffffffu, a2, o);
        a3 += __shfl_down_sync(0xffffffffu, a3, o);
    }
    if (lane==0){
        float l[4]={a0+rb[0],a1+rb[1],a2+rb[2],a3+rb[3]};
        float lm = fmaxf(fmaxf(l[0],l[1]),fmaxf(l[2],l[3]));
        float p[4]; float sum=0.f;
        #pragma unroll
        for(int e=0;e<4;e++){ p[e]=expf(l[e]-lm); sum+=p[e]; }
        #pragma unroll
        for(int e=0;e<4;e++) p[e]/=sum;
        int i0=0;
        #pragma unroll
        for(int e=1;e<4;e++) if(p[e]>p[i0]) i0=e;
        int i1=-1;
        #pragma unroll
        for(int e=0;e<4;e++){ if(e==i0) continue; if(i1<0 || p[e]>p[i1]) i1=e; }
        float gs = p[i0]+p[i1];
        float outv[4]={0.f,0.f,0.f,0.f};
        outv[i0]=p[i0]/gs; outv[i1]=p[i1]/gs;
        #pragma unroll
        for(int e=0;e<4;e++) g_gate[(size_t)t*NE+e]=outv[e];
        int pos0 = atomicAdd(&g_ecnt[i0], 1); g_eidx[i0*NT+pos0]=t;
        int pos1 = atomicAdd(&g_ecnt[i1], 1); g_eidx[i1*NT+pos1]=t;
    }
}

// ================= mma.sync bf16-split GEMM =================
// C[cm,0:N) (+)= rowscale[cm]*act( (Ah+Al)@(Bh+Bl)^T + bias )  dropping Al*Bl
// CTA 128x128, BK=32, 8 warps (2x4), warp tile 64x32, m16n8k16 HMMA.
// smem row stride 40 bf16 (80B) -> conflict-free ldmatrix.
#define TG_SMEM (2*4*128*40*2)   /* 2 bufs * 4 arrays * 128 rows * 40 bf16 * 2B = 81920 */

__global__ void __launch_bounds__(256,1) tgemm_kernel(
    const __nv_bfloat16* __restrict__ Ah, const __nv_bfloat16* __restrict__ Al, int lda,
    const __nv_bfloat16* __restrict__ Bh, const __nv_bfloat16* __restrict__ Bl, int ldb,
    float* __restrict__ C, int ldc,
    __nv_bfloat16* __restrict__ Oh, __nv_bfloat16* __restrict__ Ol, int ldo,
    int M, int N, int K,
    const float* __restrict__ bias, int act,
    const float* __restrict__ rowscale, int rs_stride, int accum,
    const int* __restrict__ gidx, const int* __restrict__ gcount, int gatherA, int scatterC)
{
    extern __shared__ __nv_bfloat16 sm[];
    int count = gcount ? *gcount : M;
    int m0 = blockIdx.y*128, n0 = blockIdx.x*128;
    if (count <= 0 || m0 >= count) return;

    int tid = threadIdx.x, wid = tid>>5, lane = tid&31;
    int wm = (wid>>2)*64, wn = (wid&3)*32;
    uint32_t smb = smem_u32(sm);

    // buffer offsets (bytes): Ah:0 Al:10240 Bh:20480 Bl:30720, buf stride 40960
    float acc[4][4][4];
    #pragma unroll
    for (int mi=0;mi<4;mi++)
        #pragma unroll
        for (int ni=0;ni<4;ni++)
            #pragma unroll
            for (int f=0;f<4;f++) acc[mi][ni][f]=0.f;

    unsigned long long stA[2][4], stB[2][4];  // [hi/lo][u]

    auto ldg_tile = [&](int kt){
        int kb = kt*32;
        #pragma unroll
        for (int u=0;u<4;u++){
            int c = tid + u*256;
            int row = c>>3, kc = (c&7)*4;
            int ar = m0+row; ar = ar<count ? ar : count-1;
            long long arow = gatherA ? gidx[ar] : ar;
            long long goff = arow*(long long)lda + kb + kc;
            stA[0][u] = *(const unsigned long long*)(Ah+goff);
            stA[1][u] = *(const unsigned long long*)(Al+goff);
            long long boff = (long long)(n0+row)*ldb + kb + kc;
            stB[0][u] = *(const unsigned long long*)(Bh+boff);
            stB[1][u] = *(const unsigned long long*)(Bl+boff);
        }
    };
    auto sts_tile = [&](int buf){
        __nv_bfloat16* base = sm + buf*20480;
        #pragma unroll
        for (int u=0;u<4;u++){
            int c = tid + u*256;
            int row = c>>3, kc = (c&7)*4;
            *(unsigned long long*)(base + row*40 + kc)         = stA[0][u];
            *(unsigned long long*)(base + 5120 + row*40 + kc)  = stA[1][u];
            *(unsigned long long*)(base + 10240 + row*40 + kc) = stB[0][u];
            *(unsigned long long*)(base + 15360 + row*40 + kc) = stB[1][u];
        }
    };

    ldg_tile(0);
    sts_tile(0);
    __syncthreads();

    int KT = K >> 5;
    int buf = 0;
    for (int kt=0; kt<KT; kt++){
        bool has_next = (kt+1) < KT;
        if (has_next) ldg_tile(kt+1);

        uint32_t bufb = smb + buf*40960u;
        #pragma unroll
        for (int ks=0; ks<2; ks++){
            // A fragments (hi & lo)
            uint32_t ah[4][4], al[4][4];
            int arow_l = (lane&7) + ((lane>>3)&1)*8;
            int akcol  = ks*16 + (lane>>4)*8;
            #pragma unroll
            for (int mi=0;mi<4;mi++){
                uint32_t off = (uint32_t)((wm + mi*16 + arow_l)*80 + akcol*2);
                LDSM_X4(ah[mi][0],ah[mi][1],ah[mi][2],ah[mi][3], bufb + off);
                LDSM_X4(al[mi][0],al[mi][1],al[mi][2],al[mi][3], bufb + 10240u + off);
            }
            // B fragments (hi & lo)
            uint32_t bh[4][2], bl[4][2];
            int brow_l = lane&7;
            int bkcol  = ks*16 + ((lane>>3)&1)*8;
            #pragma unroll
            for (int ni=0;ni<4;ni++){
                uint32_t off = (uint32_t)((wn + ni*8 + brow_l)*80 + bkcol*2);
                LDSM_X2(bh[ni][0],bh[ni][1], bufb + 20480u + off);
                LDSM_X2(bl[ni][0],bl[ni][1], bufb + 30720u + off);
            }
            #pragma unroll
            for (int mi=0;mi<4;mi++)
                #pragma unroll
                for (int ni=0;ni<4;ni++){
                    MMA16816(acc[mi][ni], ah[mi], bh[ni]);
                    MMA16816(acc[mi][ni], ah[mi], bl[ni]);
                    MMA16816(acc[mi][ni], al[mi], bh[ni]);
                }
        }

        if (has_next){
            __syncthreads();
            sts_tile(buf^1);
            __syncthreads();
            buf ^= 1;
        }
    }

    // ---- epilogue ----
    #pragma unroll
    for (int mi=0;mi<4;mi++){
        #pragma unroll
        for (int half=0; half<2; half++){
            int m = m0 + wm + mi*16 + (lane>>2) + half*8;
            if (m >= count) continue;
            long long cm = scatterC ? gidx[m] : m;
            float rs = rowscale ? rowscale[cm*(long long)rs_stride] : 1.0f;
            #pragma unroll
            for (int ni=0;ni<4;ni++){
                int n = n0 + wn + ni*8 + (lane&3)*2;
                float v0 = acc[mi][ni][half*2+0];
                float v1 = acc[mi][ni][half*2+1];
                if (bias){ v0 += bias[n]; v1 += bias[n+1]; }
                if (act){ v0 = gelu_f(v0); v1 = gelu_f(v1); }
                v0 *= rs; v1 *= rs;
                if (C){
                    long long ix = cm*(long long)ldc + n;
                    if (accum){ C[ix] += v0; C[ix+1] += v1; }
                    else      { C[ix]  = v0; C[ix+1]  = v1; }
                }
                if (Oh){
                    long long ix = cm*(long long)ldo + n;
                    __nv_bfloat16 h0,l0,h1,l1;
                    split_bf(v0,h0,l0); split_bf(v1,h1,l1);
                    Oh[ix]=h0; Ol[ix]=l0; Oh[ix+1]=h1; Ol[ix+1]=l1;
                }
            }
        }
    }
}

struct TArg {
    const __nv_bfloat16 *Ah,*Al; int lda;
    const __nv_bfloat16 *Bh,*Bl; int ldb;
    float* C; int ldc;
    __nv_bfloat16 *Oh,*Ol; int ldo;
    int M,N,K;
    const float* bias; int act;
    const float* rs; int rss; int accum;
    const int* gidx; const int* gcnt; int gA, sC;
};
static void launch_t(const TArg& a){
    dim3 grid((unsigned)(a.N/128), (unsigned)((a.M+127)/128));
    tgemm_kernel<<<grid,256,TG_SMEM>>>(a.Ah,a.Al,a.lda, a.Bh,a.Bl,a.ldb, a.C,a.ldc,
        a.Oh,a.Ol,a.ldo, a.M,a.N,a.K, a.bias,a.act, a.rs,a.rss,a.accum,
        a.gidx,a.gcnt,a.gA,a.sC);
}

// ================= f32x2 SGEMM (attention only) =================
template<int BM,int BN,int TN>
__global__ void __launch_bounds__(256,2) gemm_t(
    const float* __restrict__ A, int lda, long long sAo, long long sAi,
    const float* __restrict__ Bm, int ldb, long long sBo, long long sBi, int transB,
    float* __restrict__ C, int ldc, long long sCo, long long sCi,
    int M, int N, int K, int hdiv, float alpha)
{
    constexpr int BK = 16;
    constexpr int TM = 8;
    constexpr int NTH = 256;
    constexpr int NA  = BM*BK/(4*NTH);
    constexpr int NBt = BN*BK/(4*NTH);
    static_assert((BM/TM)*(BN/TN) == NTH, "bad tiling");

    int z = blockIdx.z;
    int zo = z / hdiv, zi = z - zo*hdiv;
    A  += zo*sAo + zi*sAi;
    Bm += zo*sBo + zi*sBi;
    C  += zo*sCo + zi*sCi;

    int m0 = blockIdx.y * BM;
    int n0 = blockIdx.x * BN;

    __shared__ float As[2][BK][BM+4];
    __shared__ float Bs[2][BK][BN+4];

    int tid = threadIdx.x;
    int tx = tid & 15;
    int ty = tid >> 4;
    int row0 = ty*TM;
    int col0 = tx*TN;

    unsigned long long acc[TM][TN/2];
    #pragma unroll
    for (int i=0;i<TM;i++)
        #pragma unroll
        for (int jp=0;jp<TN/2;jp++) acc[i][jp]=0ULL;

    float4 sa[NA], sb[NBt];
    auto ldg_tile = [&](int k0){
        #pragma unroll
        for (int u=0;u<NA;u++){
            int i = tid + u*NTH;
            int row = i >> 2;
            int kc  = (i & 3) * 4;
            sa[u] = *(const float4*)(A + (long long)(m0+row)*lda + (k0+kc));
        }
        if (transB) {
            #pragma unroll
            for (int u=0;u<NBt;u++){
                int i = tid + u*NTH;
                int n  = i >> 2;
                int kc = (i & 3) * 4;
                sb[u] = *(const float4*)(Bm + (long long)(n0+n)*ldb + (k0+kc));
            }
        } else {
            #pragma unroll
            for (int u=0;u<NBt;u++){
                int i = tid + u*NTH;
                int kr = i / (BN/4);
                int n  = (i % (BN/4)) * 4;
                sb[u] = *(const float4*)(Bm + (long long)(k0+kr)*ldb + (n0+n));
            }
        }
    };
    auto sts_tile = [&](int buf){
        #pragma unroll
        for (int u=0;u<NA;u++){
            int i = tid + u*NTH;
            int row = i >> 2;
            int kc  = (i & 3) * 4;
            As[buf][kc+0][row]=sa[u].x; As[buf][kc+1][row]=sa[u].y;
            As[buf][kc+2][row]=sa[u].z; As[buf][kc+3][row]=sa[u].w;
        }
        if (transB) {
            #pragma unroll
            for (int u=0;u<NBt;u++){
                int i = tid + u*NTH;
                int n  = i >> 2;
                int kc = (i & 3) * 4;
                Bs[buf][kc+0][n]=sb[u].x; Bs[buf][kc+1][n]=sb[u].y;
                Bs[buf][kc+2][n]=sb[u].z; Bs[buf][kc+3][n]=sb[u].w;
            }
        } else {
            #pragma unroll
            for (int u=0;u<NBt;u++){
                int i = tid + u*NTH;
                int kr = i / (BN/4);
                int n  = (i % (BN/4)) * 4;
                *(float4*)&Bs[buf][kr][n] = sb[u];
            }
        }
    };

    ldg_tile(0);
    sts_tile(0);
    __syncthreads();

    int buf = 0;
    for (int k0 = 0; k0 < K; k0 += BK) {
        bool has_next = (k0 + BK) < K;
        if (has_next) ldg_tile(k0 + BK);

        #pragma unroll
        for (int kk=0;kk<BK;kk++){
            float av[TM];
            *(float4*)&av[0] = *(const float4*)&As[buf][kk][row0];
            *(float4*)&av[4] = *(const float4*)&As[buf][kk][row0+4];
            unsigned long long bd[TN/2];
            #pragma unroll
            for (int jp=0;jp<TN/2;jp++)
                bd[jp] = *(const unsigned long long*)&Bs[buf][kk][col0+2*jp];
            #pragma unroll
            for (int i=0;i<TM;i++){
                unsigned long long ad;
                DUP2(ad, av[i]);
                #pragma unroll
                for (int jp=0;jp<TN/2;jp++)
                    FMA2(acc[i][jp], ad, bd[jp], acc[i][jp]);
            }
        }
        if (has_next) {
            sts_tile(buf ^ 1);
            __syncthreads();
            buf ^= 1;
        }
    }

    #pragma unroll
    for (int i=0;i<TM;i++){
        int m = m0 + row0 + i;
        #pragma unroll
        for (int jp=0;jp<TN/2;jp++){
            float v0, v1;
            UNP2(v0, v1, acc[i][jp]);
            int n = n0 + col0 + 2*jp;
            long long idx = (long long)m*ldc + n;
            C[idx]   = alpha*v0;
            C[idx+1] = alpha*v1;
        }
    }
}

extern "C" void kernel_launch(void* const* d_in, const int* in_sizes, int n_in,
                              void* d_out, int out_size)
{
    (void)in_sizes; (void)n_in; (void)out_size;
    const int*   text  = (const int*)  d_in[0];
    const float* embed = (const float*)d_in[1];
    const float* conv_w= (const float*)d_in[2];
    const float* conv_b= (const float*)d_in[3];
    const float* Wq    = (const float*)d_in[4];
    const float* bq    = (const float*)d_in[5];
    const float* Wk    = (const float*)d_in[6];
    const float* bk    = (const float*)d_in[7];
    const float* Wv    = (const float*)d_in[8];
    const float* bv    = (const float*)d_in[9];
    const float* Wo    = (const float*)d_in[10];
    const float* bo    = (const float*)d_in[11];
    const float* rw    = (const float*)d_in[12];
    const float* rb    = (const float*)d_in[13];
    const float* ew1   = (const float*)d_in[14];
    const float* eb1   = (const float*)d_in[15];
    const float* ew2   = (const float*)d_in[16];
    const float* eb2   = (const float*)d_in[17];
    const float* ln1g  = (const float*)d_in[18];
    const float* ln1b  = (const float*)d_in[19];
    const float* ln2g  = (const float*)d_in[20];
    const float* ln2b  = (const float*)d_in[21];
    const float* lnfg  = (const float*)d_in[22];
    const float* lnfb  = (const float*)d_in[23];
    const float* outw  = (const float*)d_in[24];
    const float* outb  = (const float*)d_in[25];
    float* out = (float*)d_out;

    cudaFuncSetAttribute(tgemm_kernel, cudaFuncAttributeMaxDynamicSharedMemorySize, TG_SMEM);

    float *x,*h,*q,*k,*v,*o,*sc,*gate;
    int *eidx,*ecnt;
    cudaGetSymbolAddress((void**)&x,  g_x);
    cudaGetSymbolAddress((void**)&h,  g_h);
    cudaGetSymbolAddress((void**)&q,  g_q);
    cudaGetSymbolAddress((void**)&k,  g_k);
    cudaGetSymbolAddress((void**)&v,  g_v);
    cudaGetSymbolAddress((void**)&o,  g_o);
    cudaGetSymbolAddress((void**)&sc, g_sc);
    cudaGetSymbolAddress((void**)&gate, g_gate);
    cudaGetSymbolAddress((void**)&eidx, g_eidx);
    cudaGetSymbolAddress((void**)&ecnt, g_ecnt);

    __nv_bfloat16 *hbh,*hbl,*obh,*obl,*xch,*xcl,*h1h,*h1l;
    __nv_bfloat16 *wch,*wcl,*wqh,*wql,*wkh,*wkl,*wvh,*wvl,*woh,*wol,*w1h,*w1l,*w2h,*w2l,*wouth,*woutl;
    cudaGetSymbolAddress((void**)&hbh, g_hb_h);  cudaGetSymbolAddress((void**)&hbl, g_hb_l);
    cudaGetSymbolAddress((void**)&obh, g_ob_h);  cudaGetSymbolAddress((void**)&obl, g_ob_l);
    cudaGetSymbolAddress((void**)&xch, g_xcb_h); cudaGetSymbolAddress((void**)&xcl, g_xcb_l);
    cudaGetSymbolAddress((void**)&h1h, g_h1b_h); cudaGetSymbolAddress((void**)&h1l, g_h1b_l);
    cudaGetSymbolAddress((void**)&wch, g_wcT_h); cudaGetSymbolAddress((void**)&wcl, g_wcT_l);
    cudaGetSymbolAddress((void**)&wqh, g_wqT_h); cudaGetSymbolAddress((void**)&wql, g_wqT_l);
    cudaGetSymbolAddress((void**)&wkh, g_wkT_h); cudaGetSymbolAddress((void**)&wkl, g_wkT_l);
    cudaGetSymbolAddress((void**)&wvh, g_wvT_h); cudaGetSymbolAddress((void**)&wvl, g_wvT_l);
    cudaGetSymbolAddress((void**)&woh, g_woT_h); cudaGetSymbolAddress((void**)&wol, g_woT_l);
    cudaGetSymbolAddress((void**)&w1h, g_w1T_h); cudaGetSymbolAddress((void**)&w1l, g_w1T_l);
    cudaGetSymbolAddress((void**)&w2h, g_w2T_h); cudaGetSymbolAddress((void**)&w2l, g_w2T_l);
    cudaGetSymbolAddress((void**)&wouth, g_woutT_h); cudaGetSymbolAddress((void**)&woutl, g_woutT_l);

    // ---- weight repack/split ----
    convw_kernel<<<(ND*3*ND+255)/256,256>>>(conv_w);
    wtrans_kernel<<<dim3(ND/32,ND/32,NL), dim3(32,8)>>>(Wq, wqh, wql, ND, ND);
    wtrans_kernel<<<dim3(ND/32,ND/32,NL), dim3(32,8)>>>(Wk, wkh, wkl, ND, ND);
    wtrans_kernel<<<dim3(ND/32,ND/32,NL), dim3(32,8)>>>(Wv, wvh, wvl, ND, ND);
    wtrans_kernel<<<dim3(ND/32,ND/32,NL), dim3(32,8)>>>(Wo, woh, wol, ND, ND);
    wtrans_kernel<<<dim3(NF/32,ND/32,NL*NE), dim3(32,8)>>>(ew1, w1h, w1l, ND, NF);
    wtrans_kernel<<<dim3(ND/32,NF/32,NL*NE), dim3(32,8)>>>(ew2, w2h, w2l, NF, ND);
    wtrans_kernel<<<dim3(NV/32,ND/32,1), dim3(32,8)>>>(outw, wouth, woutl, ND, NV);

    // ---- tokenizer ----
    embed_kernel<<<NT,256>>>(text, embed);
    xcat_kernel<<<NT,256>>>();
    {   TArg a = {xch,xcl,3*ND, wch,wcl,3*ND, x,ND, nullptr,nullptr,0,
                  NT,ND,3*ND, conv_b,1, nullptr,0, 1, nullptr,nullptr,0,0};
        launch_t(a); }

    const long long sQK = (long long)NS*ND;
    const long long sSC = (long long)NS*NS;

    for (int i=0;i<NL;i++){
        // ---- attention ----
        ln_kernel<<<NT,256>>>(x, ln1g+(size_t)i*ND, ln1b+(size_t)i*ND, h, hbh, hbl);
        {   TArg a = {hbh,hbl,ND, wqh+(size_t)i*ND*ND, wql+(size_t)i*ND*ND, ND, q,ND,
                      nullptr,nullptr,0, NT,ND,ND, bq+(size_t)i*ND,0, nullptr,0,0, nullptr,nullptr,0,0};
            launch_t(a); }
        {   TArg a = {hbh,hbl,ND, wkh+(size_t)i*ND*ND, wkl+(size_t)i*ND*ND, ND, k,ND,
                      nullptr,nullptr,0, NT,ND,ND, bk+(size_t)i*ND,0, nullptr,0,0, nullptr,nullptr,0,0};
            launch_t(a); }
        {   TArg a = {hbh,hbl,ND, wvh+(size_t)i*ND*ND, wvl+(size_t)i*ND*ND, ND, v,ND,
                      nullptr,nullptr,0, NT,ND,ND, bv+(size_t)i*ND,0, nullptr,0,0, nullptr,nullptr,0,0};
            launch_t(a); }
        // scores = 0.125 * Q @ K^T
        {   dim3 grid(NS/128, NS/128, NB*NH);
            gemm_t<128,128,8><<<grid,256>>>(q,ND,sQK,NDH, k,ND,sQK,NDH,1,
                sc,NS,(long long)NH*sSC,sSC, NS,NS,NDH, NH, 0.125f); }
        softmax_kernel<<<NB*NH*NS,256>>>();
        // O = A @ V
        {   dim3 grid(NDH/64, NS/128, NB*NH);
            gemm_t<128,64,4><<<grid,256>>>(sc,NS,(long long)NH*sSC,sSC, v,ND,sQK,NDH,0,
                o,ND,sQK,NDH, NS,NDH,NS, NH, 1.0f); }
        tobf_kernel<<<(NT*ND+255)/256,256>>>(o, obh, obl, NT*ND);
        // x += o @ Wo + bo
        {   TArg a = {obh,obl,ND, woh+(size_t)i*ND*ND, wol+(size_t)i*ND*ND, ND, x,ND,
                      nullptr,nullptr,0, NT,ND,ND, bo+(size_t)i*ND,0, nullptr,0,1, nullptr,nullptr,0,0};
            launch_t(a); }

        // ---- MoE (top-2 gathered) ----
        ln_kernel<<<NT,256>>>(x, ln2g+(size_t)i*ND, ln2b+(size_t)i*ND, h, hbh, hbl);
        zero_cnt_kernel<<<1,32>>>();
        router_kernel<<<NT/4, dim3(32,4)>>>(h, rw+(size_t)i*ND*NE, rb+(size_t)i*NE);
        for (int e=0;e<NE;e++){
            size_t wofs1 = (size_t)(i*NE+e)*NF*ND;
            size_t wofs2 = (size_t)(i*NE+e)*ND*NF;
            const float* b1 = eb1 + ((size_t)(i*NE+e))*NF;
            const float* b2 = eb2 + ((size_t)(i*NE+e))*ND;
            {   TArg a = {hbh,hbl,ND, w1h+wofs1, w1l+wofs1, ND, nullptr,0,
                          h1h,h1l,NF, NT,NF,ND, b1,1, nullptr,0,0,
                          eidx+(size_t)e*NT, ecnt+e, 1, 0};
                launch_t(a); }
            {   TArg a = {h1h,h1l,NF, w2h+wofs2, w2l+wofs2, NF, x,ND,
                          nullptr,nullptr,0, NT,ND,NF, b2,0, gate+e,NE,1,
                          eidx+(size_t)e*NT, ecnt+e, 0, 1};
                launch_t(a); }
        }
    }

    // ---- final LN + output projection ----
    ln_kernel<<<NT,256>>>(x, lnfg, lnfb, h, hbh, hbl);
    {   TArg a = {hbh,hbl,ND, wouth,woutl,ND, out,NV, nullptr,nullptr,0,
                  NT,NV,ND, outb,0, nullptr,0,0, nullptr,nullptr,0,0};
        launch_t(a); }
}

// round 6
// speedup vs baseline: 3.1350x; 1.1353x over previous
#include <cuda_runtime.h>
#include <cuda_bf16.h>
#include <math.h>
#include <stdint.h>

#define NL 4
#define NB 4
#define NS 1024
#define ND 768
#define NF 3072
#define NE 4
#define NV 256
#define NH 12
#define NDH 64
#define NT (NB*NS)
#define NQKV 2304

// ================= packed f32x2 helpers =================
#define FMA2(d,a,b,c) asm("fma.rn.f32x2 %0, %1, %2, %3;" : "=l"(d) : "l"(a), "l"(b), "l"(c))
#define MUL2(d,a,b)   asm("mul.rn.f32x2 %0, %1, %2;" : "=l"(d) : "l"(a), "l"(b))
#define DUP2(d,s)     asm("mov.b64 %0, {%1, %1};" : "=l"(d) : "f"(s))
#define UNP2(lo,hi,v) asm("mov.b64 {%0, %1}, %2;" : "=f"(lo), "=f"(hi) : "l"(v))

__device__ __forceinline__ uint32_t smem_u32(const void* p){
    uint32_t a;
    asm("{ .reg .u64 t; cvta.to.shared.u64 t, %1; cvt.u32.u64 %0, t; }" : "=r"(a) : "l"(p));
    return a;
}

// ldmatrix / mma wrappers (sm_80+, OK on compute_103)
#define LDSM_X4(r0,r1,r2,r3,addr) \
    asm volatile("ldmatrix.sync.aligned.m8n8.x4.shared.b16 {%0,%1,%2,%3}, [%4];" \
        : "=r"(r0),"=r"(r1),"=r"(r2),"=r"(r3) : "r"(addr))
#define LDSM_X2(r0,r1,addr) \
    asm volatile("ldmatrix.sync.aligned.m8n8.x2.shared.b16 {%0,%1}, [%2];" \
        : "=r"(r0),"=r"(r1) : "r"(addr))
#define MMA16816(d,a,b) \
    asm volatile("mma.sync.aligned.m16n8k16.row.col.f32.bf16.bf16.f32 " \
        "{%0,%1,%2,%3}, {%4,%5,%6,%7}, {%8,%9}, {%0,%1,%2,%3};" \
        : "+f"((d)[0]),"+f"((d)[1]),"+f"((d)[2]),"+f"((d)[3]) \
        : "r"((a)[0]),"r"((a)[1]),"r"((a)[2]),"r"((a)[3]), "r"((b)[0]),"r"((b)[1]))

// ================= scratch =================
__device__ float g_x[NT*ND];
__device__ float g_h[NT*ND];
__device__ float g_qkv[(size_t)NT*NQKV];
__device__ float g_gate[NT*NE];
__device__ float g_bqkv[NL*NQKV];
__device__ int   g_eidx[NE*NT];
__device__ int   g_ecnt[NE];

__device__ __nv_bfloat16 g_hb_h[NT*ND],  g_hb_l[NT*ND];
__device__ __nv_bfloat16 g_ob_h[NT*ND],  g_ob_l[NT*ND];
__device__ __nv_bfloat16 g_xcb_h[NT*3*ND], g_xcb_l[NT*3*ND];
__device__ __nv_bfloat16 g_h1b_h[NT*NF], g_h1b_l[NT*NF];
__device__ __nv_bfloat16 g_wcT_h[ND*3*ND], g_wcT_l[ND*3*ND];
__device__ __nv_bfloat16 g_wqkvT_h[NL*NQKV*ND], g_wqkvT_l[NL*NQKV*ND];
__device__ __nv_bfloat16 g_woT_h[NL*ND*ND], g_woT_l[NL*ND*ND];
__device__ __nv_bfloat16 g_w1T_h[NL*NE*NF*ND], g_w1T_l[NL*NE*NF*ND];
__device__ __nv_bfloat16 g_w2T_h[NL*NE*ND*NF], g_w2T_l[NL*NE*ND*NF];
__device__ __nv_bfloat16 g_woutT_h[NV*ND], g_woutT_l[NV*ND];

__device__ __forceinline__ float gelu_f(float x){
    const float c = 0.7978845608028654f;
    return 0.5f*x*(1.0f + tanhf(c*(x + 0.044715f*x*x*x)));
}
__device__ __forceinline__ void split_bf(float v, __nv_bfloat16& h, __nv_bfloat16& l){
    h = __float2bfloat16(v);
    l = __float2bfloat16(v - __bfloat162float(h));
}

// ================= small kernels =================
__global__ void embed_kernel(const int* __restrict__ text, const float* __restrict__ emb){
    int t = blockIdx.x;
    int tok = text[t];
    const float* src = emb + (size_t)tok*ND;
    float* dst = g_x + (size_t)t*ND;
    for (int d = threadIdx.x; d < ND; d += blockDim.x) dst[d] = src[d];
}

__global__ void convw_kernel(const float* __restrict__ w){
    int idx = blockIdx.x*blockDim.x + threadIdx.x;
    if (idx >= ND*3*ND) return;
    int o = idx / (3*ND);
    int r = idx % (3*ND);
    int k = r / ND, i = r % ND;
    float v = w[((size_t)o*ND + i)*3 + k];
    split_bf(v, g_wcT_h[idx], g_wcT_l[idx]);
}

// transpose+split: in [K][N] (z-stride K*N) -> out [N][K] (z-stride ozs)
__global__ void wtrans_kernel(const float* __restrict__ in, __nv_bfloat16* __restrict__ hi,
                              __nv_bfloat16* __restrict__ lo, int K, int N, long long ozs){
    __shared__ float t[32][33];
    size_t zi = (size_t)blockIdx.z*K*N;
    size_t zo = (size_t)blockIdx.z*ozs;
    int n0 = blockIdx.x*32, k0 = blockIdx.y*32;
    int tx = threadIdx.x, ty = threadIdx.y;
    #pragma unroll
    for (int j=0;j<32;j+=8)
        t[ty+j][tx] = in[zi + (size_t)(k0+ty+j)*N + (n0+tx)];
    __syncthreads();
    #pragma unroll
    for (int j=0;j<32;j+=8){
        float v = t[tx][ty+j];
        size_t oi = zo + (size_t)(n0+ty+j)*K + (k0+tx);
        __nv_bfloat16 h,l; split_bf(v,h,l);
        hi[oi]=h; lo[oi]=l;
    }
}

__global__ void bpack_kernel(const float* __restrict__ bq, const float* __restrict__ bk,
                             const float* __restrict__ bv){
    int idx = blockIdx.x*blockDim.x + threadIdx.x;
    if (idx >= NL*NQKV) return;
    int layer = idx / NQKV, c = idx % NQKV;
    float v;
    if (c < ND)            v = bq[layer*ND + c];
    else if (c < 2*ND)     v = bk[layer*ND + c - ND];
    else                   v = bv[layer*ND + c - 2*ND];
    g_bqkv[idx] = v;
}

__global__ void xcat_kernel(){
    int t = blockIdx.x;
    int s = t % NS;
    size_t base = (size_t)t*3*ND;
    for (int idx = threadIdx.x; idx < 3*ND; idx += blockDim.x) {
        int k = idx / ND, i = idx % ND;
        int sp = s + k - 1;
        float val = (sp >= 0 && sp < NS) ? g_x[(size_t)(t + k - 1)*ND + i] : 0.0f;
        __nv_bfloat16 h,l; split_bf(val,h,l);
        g_xcb_h[base+idx]=h; g_xcb_l[base+idx]=l;
    }
}

__global__ void ln_kernel(const float* __restrict__ x, const float* __restrict__ g,
                          const float* __restrict__ b, float* __restrict__ out,
                          __nv_bfloat16* __restrict__ oh, __nv_bfloat16* __restrict__ ol){
    __shared__ float red[256];
    int r = blockIdx.x;
    const float* xr = x + (size_t)r*ND;
    int tid = threadIdx.x;
    float s = 0.f;
    for (int d = tid; d < ND; d += 256) s += xr[d];
    red[tid] = s; __syncthreads();
    for (int o = 128; o > 0; o >>= 1){ if (tid < o) red[tid] += red[tid+o]; __syncthreads(); }
    float mean = red[0] / (float)ND;
    __syncthreads();
    float vs = 0.f;
    for (int d = tid; d < ND; d += 256){ float dd = xr[d]-mean; vs += dd*dd; }
    red[tid] = vs; __syncthreads();
    for (int o = 128; o > 0; o >>= 1){ if (tid < o) red[tid] += red[tid+o]; __syncthreads(); }
    float rstd = rsqrtf(red[0]/(float)ND + 1e-5f);
    size_t base = (size_t)r*ND;
    for (int d = tid; d < ND; d += 256){
        float v = (xr[d]-mean)*rstd*g[d] + b[d];
        out[base+d] = v;
        __nv_bfloat16 h,l; split_bf(v,h,l);
        oh[base+d]=h; ol[base+d]=l;
    }
}

__global__ void zero_cnt_kernel(){
    if (threadIdx.x < NE) g_ecnt[threadIdx.x] = 0;
}

__global__ void router_kernel(const float* __restrict__ h, const float* __restrict__ rw,
                              const float* __restrict__ rb){
    int t = blockIdx.x*blockDim.y + threadIdx.y;
    int lane = threadIdx.x;
    float a0=0.f,a1=0.f,a2=0.f,a3=0.f;
    const float* hr = h + (size_t)t*ND;
    for (int d = lane; d < ND; d += 32){
        float hv = hr[d];
        a0 += hv*rw[d*NE+0];
        a1 += hv*rw[d*NE+1];
        a2 += hv*rw[d*NE+2];
        a3 += hv*rw[d*NE+3];
    }
    #pragma unroll
    for (int o=16;o>0;o>>=1){
        a0 += __shfl_down_sync(0xffffffffu, a0, o);
        a1 += __shfl_down_sync(0xffffffffu, a1, o);
        a2 += __shfl_down_sync(0xffffffffu, a2, o);
        a3 += __shfl_down_sync(0xffffffffu, a3, o);
    }
    if (lane==0){
        float l[4]={a0+rb[0],a1+rb[1],a2+rb[2],a3+rb[3]};
        float lm = fmaxf(fmaxf(l[0],l[1]),fmaxf(l[2],l[3]));
        float p[4]; float sum=0.f;
        #pragma unroll
        for(int e=0;e<4;e++){ p[e]=expf(l[e]-lm); sum+=p[e]; }
        #pragma unroll
        for(int e=0;e<4;e++) p[e]/=sum;
        int i0=0;
        #pragma unroll
        for(int e=1;e<4;e++) if(p[e]>p[i0]) i0=e;
        int i1=-1;
        #pragma unroll
        for(int e=0;e<4;e++){ if(e==i0) continue; if(i1<0 || p[e]>p[i1]) i1=e; }
        float gs = p[i0]+p[i1];
        float outv[4]={0.f,0.f,0.f,0.f};
        outv[i0]=p[i0]/gs; outv[i1]=p[i1]/gs;
        #pragma unroll
        for(int e=0;e<4;e++) g_gate[(size_t)t*NE+e]=outv[e];
        int pos0 = atomicAdd(&g_ecnt[i0], 1); g_eidx[i0*NT+pos0]=t;
        int pos1 = atomicAdd(&g_ecnt[i1], 1); g_eidx[i1*NT+pos1]=t;
    }
}

// ================= fused flash attention (fp32 f32x2) =================
// grid: (NS/128, NB*NH); 256 thr; smem: Qs[64][132] Ks[64][68] Vs[64][68] Ps[64][132]
#define FL_SMEM (25600*4)
__global__ void __launch_bounds__(256,1) flash_kernel(const float* __restrict__ qkv,
        __nv_bfloat16* __restrict__ oh, __nv_bfloat16* __restrict__ ol){
    extern __shared__ float fs[];
    float* Qs = fs;          // (d, r)
    float* Ks = fs + 8448;   // (d, c)
    float* Vs = fs + 12800;  // (k, c)
    float* Ps = fs + 17152;  // (k, r)

    int qb = blockIdx.x;
    int bh = blockIdx.y;
    int b = bh / NH, hh = bh - b*NH;
    int tid = threadIdx.x;
    int tx = tid & 15, ty = tid >> 4;
    int r0 = ty*8, c0 = tx*4;
    long long tbase = (long long)b*NS + qb*128;
    int qcol = hh*64, kcol = ND + hh*64, vcol = 2*ND + hh*64;

    for (int idx = tid; idx < 128*16; idx += 256){
        int row = idx >> 4, ds = (idx & 15)*4;
        float4 qv = *(const float4*)(qkv + (tbase+row)*NQKV + qcol + ds);
        Qs[(ds+0)*132+row] = qv.x*0.125f;
        Qs[(ds+1)*132+row] = qv.y*0.125f;
        Qs[(ds+2)*132+row] = qv.z*0.125f;
        Qs[(ds+3)*132+row] = qv.w*0.125f;
    }

    float m[8], l[8];
    unsigned long long oacc[8][2];
    #pragma unroll
    for (int i=0;i<8;i++){ m[i]=-1e30f; l[i]=0.f; oacc[i][0]=0ULL; oacc[i][1]=0ULL; }

    long long kvbase = (long long)b*NS;
    for (int kt=0; kt<16; kt++){
        __syncthreads();   // previous P@V finished; Ks/Vs reusable
        for (int idx = tid; idx < 64*16; idx += 256){
            int krow = idx >> 4, ds = (idx & 15)*4;
            long long grow = (kvbase + kt*64 + krow)*NQKV;
            float4 kv = *(const float4*)(qkv + grow + kcol + ds);
            Ks[(ds+0)*68+krow] = kv.x;
            Ks[(ds+1)*68+krow] = kv.y;
            Ks[(ds+2)*68+krow] = kv.z;
            Ks[(ds+3)*68+krow] = kv.w;
            float4 vv = *(const float4*)(qkv + grow + vcol + ds);
            *(float4*)(Vs + krow*68 + ds) = vv;
        }
        __syncthreads();

        // S = Qscaled @ K^T   (8 rows x 4 keys per thread)
        unsigned long long sa[8][2];
        #pragma unroll
        for (int i=0;i<8;i++){ sa[i][0]=0ULL; sa[i][1]=0ULL; }
        #pragma unroll 4
        for (int d=0; d<64; d++){
            float av[8];
            *(float4*)&av[0] = *(const float4*)(Qs + d*132 + r0);
            *(float4*)&av[4] = *(const float4*)(Qs + d*132 + r0 + 4);
            unsigned long long k2[2];
            k2[0] = *(const unsigned long long*)(Ks + d*68 + c0);
            k2[1] = *(const unsigned long long*)(Ks + d*68 + c0 + 2);
            #pragma unroll
            for (int i=0;i<8;i++){
                unsigned long long ad; DUP2(ad, av[i]);
                FMA2(sa[i][0], ad, k2[0], sa[i][0]);
                FMA2(sa[i][1], ad, k2[1], sa[i][1]);
            }
        }

        // online softmax (row groups = 16 tx lanes within a warp half)
        #pragma unroll
        for (int i=0;i<8;i++){
            float s0,s1,s2,s3;
            UNP2(s0,s1, sa[i][0]);
            UNP2(s2,s3, sa[i][1]);
            float lm = fmaxf(fmaxf(s0,s1), fmaxf(s2,s3));
            #pragma unroll
            for (int ms=8; ms>0; ms>>=1)
                lm = fmaxf(lm, __shfl_xor_sync(0xffffffffu, lm, ms));
            float mnew = fmaxf(m[i], lm);
            float sc = expf(m[i]-mnew);
            float p0 = expf(s0-mnew), p1 = expf(s1-mnew);
            float p2 = expf(s2-mnew), p3 = expf(s3-mnew);
            float rs = (p0+p1)+(p2+p3);
            #pragma unroll
            for (int ms=8; ms>0; ms>>=1)
                rs += __shfl_xor_sync(0xffffffffu, rs, ms);
            l[i] = l[i]*sc + rs;
            m[i] = mnew;
            unsigned long long scd; DUP2(scd, sc);
            MUL2(oacc[i][0], oacc[i][0], scd);
            MUL2(oacc[i][1], oacc[i][1], scd);
            Ps[(c0+0)*132 + r0+i] = p0;
            Ps[(c0+1)*132 + r0+i] = p1;
            Ps[(c0+2)*132 + r0+i] = p2;
            Ps[(c0+3)*132 + r0+i] = p3;
        }
        __syncthreads();

        // O += P @ V
        #pragma unroll 4
        for (int k=0; k<64; k++){
            float pv[8];
            *(float4*)&pv[0] = *(const float4*)(Ps + k*132 + r0);
            *(float4*)&pv[4] = *(const float4*)(Ps + k*132 + r0 + 4);
            unsigned long long v2[2];
            v2[0] = *(const unsigned long long*)(Vs + k*68 + c0);
            v2[1] = *(const unsigned long long*)(Vs + k*68 + c0 + 2);
            #pragma unroll
            for (int i=0;i<8;i++){
                unsigned long long pd; DUP2(pd, pv[i]);
                FMA2(oacc[i][0], pd, v2[0], oacc[i][0]);
                FMA2(oacc[i][1], pd, v2[1], oacc[i][1]);
            }
        }
    }

    #pragma unroll
    for (int i=0;i<8;i++){
        float inv = 1.0f / l[i];
        float o0,o1,o2,o3;
        UNP2(o0,o1, oacc[i][0]);
        UNP2(o2,o3, oacc[i][1]);
        o0*=inv; o1*=inv; o2*=inv; o3*=inv;
        long long ixb = (tbase + r0 + i)*ND + hh*64 + c0;
        __nv_bfloat16 hb,lb;
        split_bf(o0,hb,lb); oh[ixb+0]=hb; ol[ixb+0]=lb;
        split_bf(o1,hb,lb); oh[ixb+1]=hb; ol[ixb+1]=lb;
        split_bf(o2,hb,lb); oh[ixb+2]=hb; ol[ixb+2]=lb;
        split_bf(o3,hb,lb); oh[ixb+3]=hb; ol[ixb+3]=lb;
    }
}

// ================= mma.sync bf16-split GEMM (unchanged core from R5) =================
#define TG_SMEM (2*4*128*40*2)

__global__ void __launch_bounds__(256,1) tgemm_kernel(
    const __nv_bfloat16* __restrict__ Ah, const __nv_bfloat16* __restrict__ Al, int lda,
    const __nv_bfloat16* __restrict__ Bh, const __nv_bfloat16* __restrict__ Bl, int ldb,
    float* __restrict__ C, int ldc,
    __nv_bfloat16* __restrict__ Oh, __nv_bfloat16* __restrict__ Ol, int ldo,
    int M, int N, int K,
    const float* __restrict__ bias, int act,
    const float* __restrict__ rowscale, int rs_stride, int accum,
    const int* __restrict__ gidx, const int* __restrict__ gcount, int gatherA, int scatterC)
{
    extern __shared__ __nv_bfloat16 sm[];
    int count = gcount ? *gcount : M;
    int m0 = blockIdx.y*128, n0 = blockIdx.x*128;
    if (count <= 0 || m0 >= count) return;

    int tid = threadIdx.x, wid = tid>>5, lane = tid&31;
    int wm = (wid>>2)*64, wn = (wid&3)*32;
    uint32_t smb = smem_u32(sm);

    float acc[4][4][4];
    #pragma unroll
    for (int mi=0;mi<4;mi++)
        #pragma unroll
        for (int ni=0;ni<4;ni++)
            #pragma unroll
            for (int f=0;f<4;f++) acc[mi][ni][f]=0.f;

    unsigned long long stA[2][4], stB[2][4];

    auto ldg_tile = [&](int kt){
        int kb = kt*32;
        #pragma unroll
        for (int u=0;u<4;u++){
            int c = tid + u*256;
            int row = c>>3, kc = (c&7)*4;
            int ar = m0+row; ar = ar<count ? ar : count-1;
            long long arow = gatherA ? gidx[ar] : ar;
            long long goff = arow*(long long)lda + kb + kc;
            stA[0][u] = *(const unsigned long long*)(Ah+goff);
            stA[1][u] = *(const unsigned long long*)(Al+goff);
            long long boff = (long long)(n0+row)*ldb + kb + kc;
            stB[0][u] = *(const unsigned long long*)(Bh+boff);
            stB[1][u] = *(const unsigned long long*)(Bl+boff);
        }
    };
    auto sts_tile = [&](int buf){
        __nv_bfloat16* base = sm + buf*20480;
        #pragma unroll
        for (int u=0;u<4;u++){
            int c = tid + u*256;
            int row = c>>3, kc = (c&7)*4;
            *(unsigned long long*)(base + row*40 + kc)         = stA[0][u];
            *(unsigned long long*)(base + 5120 + row*40 + kc)  = stA[1][u];
            *(unsigned long long*)(base + 10240 + row*40 + kc) = stB[0][u];
            *(unsigned long long*)(base + 15360 + row*40 + kc) = stB[1][u];
        }
    };

    ldg_tile(0);
    sts_tile(0);
    __syncthreads();

    int KT = K >> 5;
    int buf = 0;
    for (int kt=0; kt<KT; kt++){
        bool has_next = (kt+1) < KT;
        if (has_next) ldg_tile(kt+1);

        uint32_t bufb = smb + buf*40960u;
        #pragma unroll
        for (int ks=0; ks<2; ks++){
            uint32_t ah[4][4], al[4][4];
            int arow_l = (lane&7) + ((lane>>3)&1)*8;
            int akcol  = ks*16 + (lane>>4)*8;
            #pragma unroll
            for (int mi=0;mi<4;mi++){
                uint32_t off = (uint32_t)((wm + mi*16 + arow_l)*80 + akcol*2);
                LDSM_X4(ah[mi][0],ah[mi][1],ah[mi][2],ah[mi][3], bufb + off);
                LDSM_X4(al[mi][0],al[mi][1],al[mi][2],al[mi][3], bufb + 10240u + off);
            }
            uint32_t bh[4][2], bl[4][2];
            int brow_l = lane&7;
            int bkcol  = ks*16 + ((lane>>3)&1)*8;
            #pragma unroll
            for (int ni=0;ni<4;ni++){
                uint32_t off = (uint32_t)((wn + ni*8 + brow_l)*80 + bkcol*2);
                LDSM_X2(bh[ni][0],bh[ni][1], bufb + 20480u + off);
                LDSM_X2(bl[ni][0],bl[ni][1], bufb + 30720u + off);
            }
            #pragma unroll
            for (int mi=0;mi<4;mi++)
                #pragma unroll
                for (int ni=0;ni<4;ni++){
                    MMA16816(acc[mi][ni], ah[mi], bh[ni]);
                    MMA16816(acc[mi][ni], ah[mi], bl[ni]);
                    MMA16816(acc[mi][ni], al[mi], bh[ni]);
                }
        }

        if (has_next){
            __syncthreads();
            sts_tile(buf^1);
            __syncthreads();
            buf ^= 1;
        }
    }

    #pragma unroll
    for (int mi=0;mi<4;mi++){
        #pragma unroll
        for (int half=0; half<2; half++){
            int m = m0 + wm + mi*16 + (lane>>2) + half*8;
            if (m >= count) continue;
            long long cm = scatterC ? gidx[m] : m;
            float rs = rowscale ? rowscale[cm*(long long)rs_stride] : 1.0f;
            #pragma unroll
            for (int ni=0;ni<4;ni++){
                int n = n0 + wn + ni*8 + (lane&3)*2;
                float v0 = acc[mi][ni][half*2+0];
                float v1 = acc[mi][ni][half*2+1];
                if (bias){ v0 += bias[n]; v1 += bias[n+1]; }
                if (act){ v0 = gelu_f(v0); v1 = gelu_f(v1); }
                v0 *= rs; v1 *= rs;
                if (C){
                    long long ix = cm*(long long)ldc + n;
                    if (accum){ C[ix] += v0; C[ix+1] += v1; }
                    else      { C[ix]  = v0; C[ix+1]  = v1; }
                }
                if (Oh){
                    long long ix = cm*(long long)ldo + n;
                    __nv_bfloat16 h0,l0,h1,l1;
                    split_bf(v0,h0,l0); split_bf(v1,h1,l1);
                    Oh[ix]=h0; Ol[ix]=l0; Oh[ix+1]=h1; Ol[ix+1]=l1;
                }
            }
        }
    }
}

struct TArg {
    const __nv_bfloat16 *Ah,*Al; int lda;
    const __nv_bfloat16 *Bh,*Bl; int ldb;
    float* C; int ldc;
    __nv_bfloat16 *Oh,*Ol; int ldo;
    int M,N,K;
    const float* bias; int act;
    const float* rs; int rss; int accum;
    const int* gidx; const int* gcnt; int gA, sC;
};
static void launch_t(const TArg& a){
    dim3 grid((unsigned)(a.N/128), (unsigned)((a.M+127)/128));
    tgemm_kernel<<<grid,256,TG_SMEM>>>(a.Ah,a.Al,a.lda, a.Bh,a.Bl,a.ldb, a.C,a.ldc,
        a.Oh,a.Ol,a.ldo, a.M,a.N,a.K, a.bias,a.act, a.rs,a.rss,a.accum,
        a.gidx,a.gcnt,a.gA,a.sC);
}

extern "C" void kernel_launch(void* const* d_in, const int* in_sizes, int n_in,
                              void* d_out, int out_size)
{
    (void)in_sizes; (void)n_in; (void)out_size;
    const int*   text  = (const int*)  d_in[0];
    const float* embed = (const float*)d_in[1];
    const float* conv_w= (const float*)d_in[2];
    const float* conv_b= (const float*)d_in[3];
    const float* Wq    = (const float*)d_in[4];
    const float* bq    = (const float*)d_in[5];
    const float* Wk    = (const float*)d_in[6];
    const float* bk    = (const float*)d_in[7];
    const float* Wv    = (const float*)d_in[8];
    const float* bv    = (const float*)d_in[9];
    const float* Wo    = (const float*)d_in[10];
    const float* bo    = (const float*)d_in[11];
    const float* rw    = (const float*)d_in[12];
    const float* rb    = (const float*)d_in[13];
    const float* ew1   = (const float*)d_in[14];
    const float* eb1   = (const float*)d_in[15];
    const float* ew2   = (const float*)d_in[16];
    const float* eb2   = (const float*)d_in[17];
    const float* ln1g  = (const float*)d_in[18];
    const float* ln1b  = (const float*)d_in[19];
    const float* ln2g  = (const float*)d_in[20];
    const float* ln2b  = (const float*)d_in[21];
    const float* lnfg  = (const float*)d_in[22];
    const float* lnfb  = (const float*)d_in[23];
    const float* outw  = (const float*)d_in[24];
    const float* outb  = (const float*)d_in[25];
    float* out = (float*)d_out;

    cudaFuncSetAttribute(tgemm_kernel, cudaFuncAttributeMaxDynamicSharedMemorySize, TG_SMEM);
    cudaFuncSetAttribute(flash_kernel, cudaFuncAttributeMaxDynamicSharedMemorySize, FL_SMEM);

    float *x,*h,*qkv,*gate,*bqkv;
    int *eidx,*ecnt;
    cudaGetSymbolAddress((void**)&x,  g_x);
    cudaGetSymbolAddress((void**)&h,  g_h);
    cudaGetSymbolAddress((void**)&qkv, g_qkv);
    cudaGetSymbolAddress((void**)&gate, g_gate);
    cudaGetSymbolAddress((void**)&bqkv, g_bqkv);
    cudaGetSymbolAddress((void**)&eidx, g_eidx);
    cudaGetSymbolAddress((void**)&ecnt, g_ecnt);

    __nv_bfloat16 *hbh,*hbl,*obh,*obl,*xch,*xcl,*h1h,*h1l;
    __nv_bfloat16 *wch,*wcl,*wqkvh,*wqkvl,*woh,*wol,*w1h,*w1l,*w2h,*w2l,*wouth,*woutl;
    cudaGetSymbolAddress((void**)&hbh, g_hb_h);  cudaGetSymbolAddress((void**)&hbl, g_hb_l);
    cudaGetSymbolAddress((void**)&obh, g_ob_h);  cudaGetSymbolAddress((void**)&obl, g_ob_l);
    cudaGetSymbolAddress((void**)&xch, g_xcb_h); cudaGetSymbolAddress((void**)&xcl, g_xcb_l);
    cudaGetSymbolAddress((void**)&h1h, g_h1b_h); cudaGetSymbolAddress((void**)&h1l, g_h1b_l);
    cudaGetSymbolAddress((void**)&wch, g_wcT_h); cudaGetSymbolAddress((void**)&wcl, g_wcT_l);
    cudaGetSymbolAddress((void**)&wqkvh, g_wqkvT_h); cudaGetSymbolAddress((void**)&wqkvl, g_wqkvT_l);
    cudaGetSymbolAddress((void**)&woh, g_woT_h); cudaGetSymbolAddress((void**)&wol, g_woT_l);
    cudaGetSymbolAddress((void**)&w1h, g_w1T_h); cudaGetSymbolAddress((void**)&w1l, g_w1T_l);
    cudaGetSymbolAddress((void**)&w2h, g_w2T_h); cudaGetSymbolAddress((void**)&w2l, g_w2T_l);
    cudaGetSymbolAddress((void**)&wouth, g_woutT_h); cudaGetSymbolAddress((void**)&woutl, g_woutT_l);

    const long long LQKV = (long long)NQKV*ND;   // per-layer packed-qkv weight stride
    const long long LDD  = (long long)ND*ND;

    // ---- weight repack/split ----
    convw_kernel<<<(ND*3*ND+255)/256,256>>>(conv_w);
    // pack Wq/Wk/Wv into [2304][768] per layer
    wtrans_kernel<<<dim3(ND/32,ND/32,NL), dim3(32,8)>>>(Wq, wqkvh,            wqkvl,            ND, ND, LQKV);
    wtrans_kernel<<<dim3(ND/32,ND/32,NL), dim3(32,8)>>>(Wk, wqkvh+(size_t)ND*ND, wqkvl+(size_t)ND*ND, ND, ND, LQKV);
    wtrans_kernel<<<dim3(ND/32,ND/32,NL), dim3(32,8)>>>(Wv, wqkvh+(size_t)2*ND*ND, wqkvl+(size_t)2*ND*ND, ND, ND, LQKV);
    wtrans_kernel<<<dim3(ND/32,ND/32,NL), dim3(32,8)>>>(Wo, woh, wol, ND, ND, LDD);
    wtrans_kernel<<<dim3(NF/32,ND/32,NL*NE), dim3(32,8)>>>(ew1, w1h, w1l, ND, NF, (long long)ND*NF);
    wtrans_kernel<<<dim3(ND/32,NF/32,NL*NE), dim3(32,8)>>>(ew2, w2h, w2l, NF, ND, (long long)NF*ND);
    wtrans_kernel<<<dim3(NV/32,ND/32,1), dim3(32,8)>>>(outw, wouth, woutl, ND, NV, (long long)ND*NV);
    bpack_kernel<<<(NL*NQKV+255)/256,256>>>(bq, bk, bv);

    // ---- tokenizer ----
    embed_kernel<<<NT,256>>>(text, embed);
    xcat_kernel<<<NT,256>>>();
    {   TArg a = {xch,xcl,3*ND, wch,wcl,3*ND, x,ND, nullptr,nullptr,0,
                  NT,ND,3*ND, conv_b,1, nullptr,0, 1, nullptr,nullptr,0,0};
        launch_t(a); }

    for (int i=0;i<NL;i++){
        // ---- attention ----
        ln_kernel<<<NT,256>>>(x, ln1g+(size_t)i*ND, ln1b+(size_t)i*ND, h, hbh, hbl);
        // fused QKV projection: [T,768] @ [768,2304]
        {   TArg a = {hbh,hbl,ND, wqkvh+(size_t)i*LQKV, wqkvl+(size_t)i*LQKV, ND, qkv,NQKV,
                      nullptr,nullptr,0, NT,NQKV,ND, bqkv+(size_t)i*NQKV,0, nullptr,0,0, nullptr,nullptr,0,0};
            launch_t(a); }
        // fused flash attention -> ob split
        flash_kernel<<<dim3(NS/128, NB*NH),256,FL_SMEM>>>(qkv, obh, obl);
        // x += o @ Wo + bo
        {   TArg a = {obh,obl,ND, woh+(size_t)i*LDD, wol+(size_t)i*LDD, ND, x,ND,
                      nullptr,nullptr,0, NT,ND,ND, bo+(size_t)i*ND,0, nullptr,0,1, nullptr,nullptr,0,0};
            launch_t(a); }

        // ---- MoE (top-2 gathered) ----
        ln_kernel<<<NT,256>>>(x, ln2g+(size_t)i*ND, ln2b+(size_t)i*ND, h, hbh, hbl);
        zero_cnt_kernel<<<1,32>>>();
        router_kernel<<<NT/4, dim3(32,4)>>>(h, rw+(size_t)i*ND*NE, rb+(size_t)i*NE);
        for (int e=0;e<NE;e++){
            size_t wofs1 = (size_t)(i*NE+e)*NF*ND;
            size_t wofs2 = (size_t)(i*NE+e)*ND*NF;
            const float* b1 = eb1 + ((size_t)(i*NE+e))*NF;
            const float* b2 = eb2 + ((size_t)(i*NE+e))*ND;
            {   TArg a = {hbh,hbl,ND, w1h+wofs1, w1l+wofs1, ND, nullptr,0,
                          h1h,h1l,NF, NT,NF,ND, b1,1, nullptr,0,0,
                          eidx+(size_t)e*NT, ecnt+e, 1, 0};
                launch_t(a); }
            {   TArg a = {h1h,h1l,NF, w2h+wofs2, w2l+wofs2, NF, x,ND,
                          nullptr,nullptr,0, NT,ND,NF, b2,0, gate+e,NE,1,
                          eidx+(size_t)e*NT, ecnt+e, 0, 1};
                launch_t(a); }
        }
    }

    // ---- final LN + output projection ----
    ln_kernel<<<NT,256>>>(x, lnfg, lnfb, h, hbh, hbl);
    {   TArg a = {hbh,hbl,ND, wouth,woutl,ND, out,NV, nullptr,nullptr,0,
                  NT,NV,ND, outb,0, nullptr,0,0, nullptr,nullptr,0,0};
        launch_t(a); }
}